// round 11
// baseline (speedup 1.0000x reference)
#include <cuda_runtime.h>
#include <math.h>
#include <stdint.h>

#define Bsz 2048
#define NTHREADS 256
#define HWS 132

typedef unsigned long long ull;

// ---- smem layout (float offsets) ----
#define O_U_   16896
#define O_HW   0        // 16896 : HW row-major stride 132
#define O_U    16896    // 9216 union region:
                        //  phase0/1: WBF (W64 frag) 8192 @ +0 ; X1t frag 1024 @ +8192
                        //  GNN1 : scrZ (Z1, stride 33) 4224 @ +0 ; Wct frag 512 @ +5376 ;
                        //          part 512 @ +5888
                        //  ph2/3: VBF frag 4096 @ +0 ; z2 [k][36] 4608 @ +4096
                        //  ph4/5: P0 640 @ +0 ; Gfh 1024 @ +640 ; Gfl 1024 @ +1664 ;
                        //          dacc 256 @ +2688   (z2s @ +4096 still live in ph4)
#define O_XS   26112    // 640
#define O_SX1  26752    // 640 (SX1, later HWG)
#define O_SW   27392    // 1088
#define O_CC   28480    // 128
#define O_RED  28608    // 64
#define SMEM_FLOATS 28672
#define SMEM_BYTES (SMEM_FLOATS * 4)   // 114688 B -> 2 CTAs/SM

__device__ __forceinline__ ull dup2(float x) {
    ull r; asm("mov.b64 %0, {%1, %1};" : "=l"(r) : "f"(x)); return r;
}
#define FMA2(acc, a, b) asm("fma.rn.f32x2 %0, %1, %2, %0;" : "+l"(acc) : "l"(a), "l"(b))
__device__ __forceinline__ float hadd2(ull v) {
    float lo, hi; asm("mov.b64 {%0, %1}, %2;" : "=f"(lo), "=f"(hi) : "l"(v)); return lo + hi;
}
__device__ __forceinline__ uint32_t tf32r(float x) {
    uint32_t u; asm("cvt.rna.tf32.f32 %0, %1;" : "=r"(u) : "f"(x)); return u;
}
__device__ __forceinline__ void mma_tf32(float* c, const uint32_t* a, uint32_t b0, uint32_t b1) {
    asm volatile(
        "mma.sync.aligned.m16n8k8.row.col.f32.tf32.tf32.f32 "
        "{%0,%1,%2,%3}, {%4,%5,%6,%7}, {%8,%9}, {%0,%1,%2,%3};"
        : "+f"(c[0]), "+f"(c[1]), "+f"(c[2]), "+f"(c[3])
        : "r"(a[0]), "r"(a[1]), "r"(a[2]), "r"(a[3]), "r"(b0), "r"(b1));
}

__global__ __launch_bounds__(NTHREADS, 2)
void unfold_pocs_kernel(const float* __restrict__ gHW, const float* __restrict__ gx0,
                        const float* __restrict__ gnu3, const float* __restrict__ gtg,
                        const float* __restrict__ g1W0a, const float* __restrict__ g1W1a,
                        const float* __restrict__ g1W0b, const float* __restrict__ g1W1b,
                        const float* __restrict__ g2W0a, const float* __restrict__ g2W1a,
                        const float* __restrict__ g2W0b, const float* __restrict__ g2W1b,
                        float* __restrict__ out) {
    extern __shared__ float sm[];
    const int b = blockIdx.x;
    const int tid = threadIdx.x;
    const int wid = tid >> 5;
    const int lid = tid & 31;
    const int lr = lid >> 2;   // 0..7
    const int lc = lid & 3;    // 0..3

    float* HWs = sm + O_HW;
    float* U   = sm + O_U;
    float* xs  = sm + O_XS;
    float* sx1 = sm + O_SX1;
    float* sw  = sm + O_SW;
    float* cC  = sm + O_CC;
    float* red = sm + O_RED;

    const float* hwg = gHW + (size_t)b * (128 * 128);

    // ================= Phase 0: loads =================
    for (int o = tid; o < 4096; o += NTHREADS) {
        float4 v = *(const float4*)(hwg + o * 4);
        int w = o * 4;
        int row = w >> 7, col = w & 127;
        *(float4*)&HWs[row * HWS + col] = v;
    }
    for (int o = tid; o < 160; o += NTHREADS)
        *(float4*)&xs[o * 4] = *(const float4*)(gx0 + (size_t)b * 640 + o * 4);
    // W64 fragment-ordered into U+0 (vectorized gmem loads)
    {
        float* WBF = U;
        for (int o = tid; o < 1024; o += NTHREADS) {
            int k = o >> 3, h4 = (o & 7) * 4;
            float4 v0 = *(const float4*)&g2W0a[k * 32 + h4];
            float4 v1 = *(const float4*)&g2W1a[k * 32 + h4];
            int basek = (k >> 4) * 8;
            int comp  = (k >> 2) & 3;
            int l0    = (((h4 & 7) * 4 + (k & 3)) << 2) + comp;
            int c0 = (basek + (h4 >> 3)) << 7;
            int c1 = (basek + 4 + (h4 >> 3)) << 7;
            WBF[c0 + l0]      = v0.x;
            WBF[c0 + l0 + 16] = v0.y;
            WBF[c0 + l0 + 32] = v0.z;
            WBF[c0 + l0 + 48] = v0.w;
            WBF[c1 + l0]      = v1.x;
            WBF[c1 + l0 + 16] = v1.y;
            WBF[c1 + l0 + 32] = v1.z;
            WBF[c1 + l0 + 48] = v1.w;
        }
    }
    // X1t frag (N=8) into U+8192, read straight from gmem (no smem race)
    {
        float* X1t = U + 8192;
        const float* gx = gx0 + (size_t)b * 640;
        for (int o = tid; o < 1024; o += NTHREADS) {
            int k = o >> 3, f = o & 7;
            float v = (f < 5) ? gx[f * 128 + k] : 0.f;
            int pos = ((k >> 4) << 7) | ((f * 4 + (k & 3)) << 2) | ((k >> 2) & 3);
            X1t[pos] = v;
        }
    }
    for (int o = tid; o < 160; o += NTHREADS) sw[o]       = g1W0a[o];
    for (int o = tid; o < 160; o += NTHREADS) sw[160 + o] = g1W1a[o];
    for (int o = tid; o < 64;  o += NTHREADS) sw[320 + o] = g1W0b[o];
    for (int o = tid; o < 64;  o += NTHREADS) sw[384 + o] = g1W1b[o];
    for (int o = tid; o < 160; o += NTHREADS) sw[448 + o] = g2W0a[128 * 32 + o];
    for (int o = tid; o < 160; o += NTHREADS) sw[608 + o] = g2W1a[128 * 32 + o];
    for (int o = tid; o < 160; o += NTHREADS) {
        int f = o >> 5, h = o & 31;
        sw[768 + f * 32 + h] = g2W0b[h * 5 + f];
        sw[928 + f * 32 + h] = g2W1b[h * 5 + f];
    }
    __syncthreads();

    float acc[8][4];     // T fragments, then U0 in acc[0..3]
    float acc2[4][4];    // phase1: acc2[0] = SX1 tile ; later HW@V fragments
    const int m0 = wid * 16;

    // ================= Phase 1: [T | SX1] = HW @ [W64 | X1] via HMMA tf32 =================
    {
        const float* WBF = U;
        const float* X1t = U + 8192;
#pragma unroll
        for (int nt = 0; nt < 8; nt++)
#pragma unroll
            for (int c = 0; c < 4; c++) acc[nt][c] = 0.f;
#pragma unroll
        for (int c = 0; c < 4; c++) acc2[0][c] = 0.f;
#pragma unroll
        for (int kc = 0; kc < 8; kc++) {
            const int k0 = kc * 16;
            uint32_t a0[4], a1[4];
            a0[0] = __float_as_uint(HWs[(m0 + lr)     * HWS + k0 + lc]);
            a0[1] = __float_as_uint(HWs[(m0 + lr + 8) * HWS + k0 + lc]);
            a0[2] = __float_as_uint(HWs[(m0 + lr)     * HWS + k0 + lc + 4]);
            a0[3] = __float_as_uint(HWs[(m0 + lr + 8) * HWS + k0 + lc + 4]);
            a1[0] = __float_as_uint(HWs[(m0 + lr)     * HWS + k0 + 8 + lc]);
            a1[1] = __float_as_uint(HWs[(m0 + lr + 8) * HWS + k0 + 8 + lc]);
            a1[2] = __float_as_uint(HWs[(m0 + lr)     * HWS + k0 + 12 + lc]);
            a1[3] = __float_as_uint(HWs[(m0 + lr + 8) * HWS + k0 + 12 + lc]);
#pragma unroll
            for (int nt = 0; nt < 8; nt++) {
                float4 bv = *(const float4*)&WBF[((kc << 3) + nt) << 7 | (lid << 2)];
                mma_tf32(acc[nt], a0, __float_as_uint(bv.x), __float_as_uint(bv.y));
                mma_tf32(acc[nt], a1, __float_as_uint(bv.z), __float_as_uint(bv.w));
            }
            {
                float4 bv = *(const float4*)&X1t[(kc << 7) | (lid << 2)];
                mma_tf32(acc2[0], a0, __float_as_uint(bv.x), __float_as_uint(bv.y));
                mma_tf32(acc2[0], a1, __float_as_uint(bv.z), __float_as_uint(bv.w));
            }
        }
        // write SX1
        int f0 = 2 * lc, f1 = 2 * lc + 1;
        if (f0 < 5) {
            sx1[f0 * 128 + m0 + lr]     = acc2[0][0];
            sx1[f0 * 128 + m0 + lr + 8] = acc2[0][2];
        }
        if (f1 < 5) {
            sx1[f1 * 128 + m0 + lr]     = acc2[0][1];
            sx1[f1 * 128 + m0 + lr + 8] = acc2[0][3];
        }
    }
    __syncthreads();   // WBF/X1t dead; sx1 = SX1 ready

    // ================= GNN1 (HMMA) =================
    {
        float* scrZ = U;          // Z1, stride 33
        float* Wct  = U + 5376;   // cat-weights frag (k=16, N=32)
        float* part = U + 5888;

        // build Wct: B[k][h], k<5 -> W0a[k][h], k<10 -> W1a[k-5][h], else 0
        for (int o = tid; o < 512; o += NTHREADS) {
            int h = o >> 4, k = o & 15;
            float v = (k < 5) ? sw[k * 32 + h] : (k < 10 ? sw[160 + (k - 5) * 32 + h] : 0.f);
            int pos = ((h >> 3) << 7) | (((h & 7) * 4 + (k & 3)) << 2) | ((k >> 2) & 3);
            Wct[pos] = v;
        }
        if (tid < 128) {
            float a = 0.f;
#pragma unroll 4
            for (int i = 0; i < 128; i++) a += HWs[i * HWS + tid];
            cC[tid] = a * (1.f / 128.f);
        }
        __syncthreads();

        // Z1 = relu(cat @ Wct) via HMMA, cat = [X1 | SX1] (k=10 pad 16)
        {
            const int row0 = m0 + lr, row1 = m0 + lr + 8;
            uint32_t a0[4], a1[4];
            a0[0] = __float_as_uint(xs[lc * 128 + row0]);
            a0[1] = __float_as_uint(xs[lc * 128 + row1]);
            a0[2] = __float_as_uint((lc == 0) ? xs[4 * 128 + row0] : sx1[(lc - 1) * 128 + row0]);
            a0[3] = __float_as_uint((lc == 0) ? xs[4 * 128 + row1] : sx1[(lc - 1) * 128 + row1]);
            a1[0] = (lc < 2) ? __float_as_uint(sx1[(lc + 3) * 128 + row0]) : 0u;
            a1[1] = (lc < 2) ? __float_as_uint(sx1[(lc + 3) * 128 + row1]) : 0u;
            a1[2] = 0u;
            a1[3] = 0u;
            float cz[4][4];
#pragma unroll
            for (int nt = 0; nt < 4; nt++) {
#pragma unroll
                for (int c = 0; c < 4; c++) cz[nt][c] = 0.f;
                float4 bv = *(const float4*)&Wct[(nt << 7) | (lid << 2)];
                mma_tf32(cz[nt], a0, __float_as_uint(bv.x), __float_as_uint(bv.y));
                mma_tf32(cz[nt], a1, __float_as_uint(bv.z), __float_as_uint(bv.w));
            }
#pragma unroll
            for (int nt = 0; nt < 4; nt++) {
                const int h0 = nt * 8 + 2 * lc;
                scrZ[row0 * 33 + h0]     = fmaxf(cz[nt][0], 0.f);
                scrZ[row0 * 33 + h0 + 1] = fmaxf(cz[nt][1], 0.f);
                scrZ[row1 * 33 + h0]     = fmaxf(cz[nt][2], 0.f);
                scrZ[row1 * 33 + h0 + 1] = fmaxf(cz[nt][3], 0.f);
            }
        }
        __syncthreads();

        // mean/cZ1 partials (256 threads)
        {
            const int h = tid & 31, q = tid >> 5;
            float m = 0.f, cz = 0.f;
#pragma unroll 4
            for (int k = q * 16; k < q * 16 + 16; k++) {
                float zv = scrZ[k * 33 + h];
                m += zv;
                cz += cC[k] * zv;
            }
            part[q * 32 + h] = m;
            part[256 + q * 32 + h] = cz;
        }
        __syncthreads();
        if (tid < 32) {
            float m = 0.f, cz = 0.f;
#pragma unroll
            for (int q = 0; q < 8; q++) {
                m  += part[q * 32 + tid];
                cz += part[256 + q * 32 + tid];
            }
            red[tid] = m * (1.f / 128.f);
            red[32 + tid] = cz;
        }
        __syncthreads();
        if (tid < 2) {
            const float* w0b = sw + 320;
            const float* w1b = sw + 384;
            float a = 0.f;
#pragma unroll 8
            for (int h = 0; h < 32; h++)
                a += red[h] * w0b[h * 2 + tid] + red[32 + h] * w1b[h * 2 + tid];
            red[62 + tid] = fmaxf(a, 0.f);   // lbd
        }
        __syncthreads();
        if (tid < 128) {
            float l0 = red[62], l1 = red[63];
            float s1v = xs[128 + tid];
            xs[128 + tid] = s1v - l0 * ((1.0f / 128.f) / (1.f + s1v));
            xs[512 + tid] += l1 * ((1.0f / 128.f) * 0.1f);
        }
    }
    __syncthreads();   // xs final

    // ================= Phase 2+3: U0 in regs, V frag, HMMA HW@V, z2 =================
    {
        float* VBF = U;            // V fragment order (N=32 -> 4 n-tiles)
        float* z2s = U + 4096;     // [k][36]
        const float* w0bot = sw + 448;
        const float* w1bot = sw + 608;
        float xr[2][5];
#pragma unroll
        for (int f = 0; f < 5; f++) {
            xr[0][f] = xs[f * 128 + m0 + lr];
            xr[1][f] = xs[f * 128 + m0 + lr + 8];
        }
        const int lr3 = lr & 3, lrh = lr >> 2;
#pragma unroll
        for (int nt = 0; nt < 8; nt++) {
            const bool isU = nt < 4;
            const float* wb = isU ? w0bot : w1bot;
            const int hb = (isU ? nt : nt - 4) * 8 + 2 * lc;
            float r00 = acc[nt][0], r01 = acc[nt][1];
            float r10 = acc[nt][2], r11 = acc[nt][3];
#pragma unroll
            for (int f = 0; f < 5; f++) {
                float w0 = wb[f * 32 + hb], w1 = wb[f * 32 + hb + 1];
                r00 += xr[0][f] * w0; r01 += xr[0][f] * w1;
                r10 += xr[1][f] * w0; r11 += xr[1][f] * w1;
            }
            if (isU) {
                acc[nt][0] = r00; acc[nt][1] = r01; acc[nt][2] = r10; acc[nt][3] = r11;
            } else {
                const int ch = ((wid * 4) + (nt - 4)) << 7;
                const int p0 = ch | (((2 * lc) * 4 + lr3) << 2);
                const int p1 = ch | (((2 * lc + 1) * 4 + lr3) << 2);
                VBF[p0 + lrh]     = r00;
                VBF[p1 + lrh]     = r01;
                VBF[p0 + 2 + lrh] = r10;
                VBF[p1 + 2 + lrh] = r11;
            }
        }
        __syncthreads();   // V fully written

        // HW @ V full-K via HMMA, frag B
#pragma unroll
        for (int nt = 0; nt < 4; nt++)
#pragma unroll
            for (int c = 0; c < 4; c++) acc2[nt][c] = 0.f;
#pragma unroll
        for (int kc = 0; kc < 8; kc++) {
            const int k0 = kc * 16;
            uint32_t a0[4], a1[4];
            a0[0] = __float_as_uint(HWs[(m0 + lr)     * HWS + k0 + lc]);
            a0[1] = __float_as_uint(HWs[(m0 + lr + 8) * HWS + k0 + lc]);
            a0[2] = __float_as_uint(HWs[(m0 + lr)     * HWS + k0 + lc + 4]);
            a0[3] = __float_as_uint(HWs[(m0 + lr + 8) * HWS + k0 + lc + 4]);
            a1[0] = __float_as_uint(HWs[(m0 + lr)     * HWS + k0 + 8 + lc]);
            a1[1] = __float_as_uint(HWs[(m0 + lr + 8) * HWS + k0 + 8 + lc]);
            a1[2] = __float_as_uint(HWs[(m0 + lr)     * HWS + k0 + 12 + lc]);
            a1[3] = __float_as_uint(HWs[(m0 + lr + 8) * HWS + k0 + 12 + lc]);
#pragma unroll
            for (int nt = 0; nt < 4; nt++) {
                float4 bv = *(const float4*)&VBF[((kc << 2) + nt) << 7 | (lid << 2)];
                mma_tf32(acc2[nt], a0, __float_as_uint(bv.x), __float_as_uint(bv.y));
                mma_tf32(acc2[nt], a1, __float_as_uint(bv.z), __float_as_uint(bv.w));
            }
        }
        // z2 = relu(U0 + HW@V)
#pragma unroll
        for (int nt = 0; nt < 4; nt++) {
            const int hb = nt * 8 + 2 * lc;
            *(float2*)&z2s[(m0 + lr) * 36 + hb] =
                make_float2(fmaxf(acc[nt][0] + acc2[nt][0], 0.f),
                            fmaxf(acc[nt][1] + acc2[nt][1], 0.f));
            *(float2*)&z2s[(m0 + lr + 8) * 36 + hb] =
                make_float2(fmaxf(acc[nt][2] + acc2[nt][2], 0.f),
                            fmaxf(acc[nt][3] + acc2[nt][3], 0.f));
        }
    }
    __syncthreads();

    // ================= Phase 4: G (hi/lo frag) = Z2@W1b, P0 = Z2@W0b =================
    {
        const float* z2s = U + 4096;
        float* P0  = U;
        float* Gfh = U + 640;
        float* Gfl = U + 1664;
        for (int o = tid; o < 1024; o += NTHREADS) {
            int k = o & 127, f = o >> 7;    // f 0..7
            int pos = ((k >> 4) << 7) | ((f * 4 + (k & 3)) << 2) | ((k >> 2) & 3);
            if (f < 5) {
                const float* zr  = &z2s[k * 36];
                const float* wp0 = &sw[768 + f * 32];
                const float* wp1 = &sw[928 + f * 32];
                ull g2a = 0ull, p2a = 0ull;
#pragma unroll
                for (int h = 0; h < 32; h += 4) {
                    ulonglong2 zv  = *(const ulonglong2*)&zr[h];
                    ulonglong2 w1v = *(const ulonglong2*)&wp1[h];
                    ulonglong2 w0v = *(const ulonglong2*)&wp0[h];
                    FMA2(g2a, zv.x, w1v.x);
                    FMA2(g2a, zv.y, w1v.y);
                    FMA2(p2a, zv.x, w0v.x);
                    FMA2(p2a, zv.y, w0v.y);
                }
                float g = hadd2(g2a);
                float gh = __uint_as_float(tf32r(g));
                Gfh[pos] = gh;
                Gfl[pos] = g - gh;
                P0[f * 128 + k] = hadd2(p2a);
            } else {
                Gfh[pos] = 0.f;
                Gfl[pos] = 0.f;
            }
        }
    }
    __syncthreads();

    // ================= Phase 5: HWG = HW@G via HMMA (3-term tf32 split) =================
    {
        const float* Gfh = U + 640;
        const float* Gfl = U + 1664;
        float c[4] = {0.f, 0.f, 0.f, 0.f};
#pragma unroll
        for (int kc = 0; kc < 8; kc++) {
            const int k0 = kc * 16;
            float af[8];
            af[0] = HWs[(m0 + lr)     * HWS + k0 + lc];
            af[1] = HWs[(m0 + lr + 8) * HWS + k0 + lc];
            af[2] = HWs[(m0 + lr)     * HWS + k0 + lc + 4];
            af[3] = HWs[(m0 + lr + 8) * HWS + k0 + lc + 4];
            af[4] = HWs[(m0 + lr)     * HWS + k0 + 8 + lc];
            af[5] = HWs[(m0 + lr + 8) * HWS + k0 + 8 + lc];
            af[6] = HWs[(m0 + lr)     * HWS + k0 + 12 + lc];
            af[7] = HWs[(m0 + lr + 8) * HWS + k0 + 12 + lc];
            uint32_t ah[8], al[8];
#pragma unroll
            for (int i = 0; i < 8; i++) {
                ah[i] = tf32r(af[i]);
                al[i] = __float_as_uint(af[i] - __uint_as_float(ah[i]));
            }
            float4 bh = *(const float4*)&Gfh[(kc << 7) | (lid << 2)];
            float4 bl = *(const float4*)&Gfl[(kc << 7) | (lid << 2)];
            uint32_t bh0 = __float_as_uint(bh.x), bh1 = __float_as_uint(bh.y);
            uint32_t bh2 = __float_as_uint(bh.z), bh3 = __float_as_uint(bh.w);
            uint32_t bl0 = __float_as_uint(bl.x), bl1 = __float_as_uint(bl.y);
            uint32_t bl2 = __float_as_uint(bl.z), bl3 = __float_as_uint(bl.w);
            mma_tf32(c, ah,     bh0, bh1);
            mma_tf32(c, ah,     bl0, bl1);
            mma_tf32(c, al,     bh0, bh1);
            mma_tf32(c, ah + 4, bh2, bh3);
            mma_tf32(c, ah + 4, bl2, bl3);
            mma_tf32(c, al + 4, bh2, bh3);
        }
        int f0 = 2 * lc, f1 = 2 * lc + 1;
        if (f0 < 5) {
            sx1[f0 * 128 + m0 + lr]     = c[0];
            sx1[f0 * 128 + m0 + lr + 8] = c[2];
        }
        if (f1 < 5) {
            sx1[f1 * 128 + m0 + lr]     = c[1];
            sx1[f1 * 128 + m0 + lr + 8] = c[3];
        }
    }
    __syncthreads();
    for (int o = tid; o < 640; o += NTHREADS)
        xs[o] += U[o] + sx1[o];
    __syncthreads();

    // ================= band-0 sum =================
    if (tid < 32) {
        float s = xs[tid] + xs[tid + 32] + xs[tid + 64] + xs[tid + 96];
#pragma unroll
        for (int m = 16; m > 0; m >>= 1) s += __shfl_xor_sync(0xffffffffu, s, m);
        if (tid == 0) red[0] = s;
    }
    __syncthreads();

    // ================= projection + band clamps =================
    {
        float fproj = red[0] - 10.0f;
        float nu3 = gnu3[0], tg = gtg[0];
        float Vnu = 1.f - 1.f / ((1.f + nu3) * (1.f + nu3));
        float Vg  = 1.f - 1.f / ((1.f + tg) * (1.f + tg));
        for (int m = tid; m < 640; m += NTHREADS) {
            float v = xs[m];
            int band = m >> 7;
            if (band == 0 && fproj > 0.f) v -= fproj * (1.f / 128.f);
            v = fmaxf(v, band == 1 ? nu3 : 0.f);
            if (band == 2) v = fminf(v, tg);
            if (band == 3) v = fminf(fmaxf(v, Vnu), Vg);
            xs[m] = v;
        }
    }
    __syncthreads();

    // ================= outputs =================
    {
        float* outx = out + (size_t)b * 640;
        for (int o = tid; o < 160; o += NTHREADS)
            *(float4*)&outx[o * 4] = *(const float4*)&xs[o * 4];
        float* dp = U + 2688;
        const int k = tid & 127, q = tid >> 7;
        float a = 0.f;
#pragma unroll 8
        for (int i = 64 * q; i < 64 * q + 64; i++)
            a += xs[i] * HWs[i * HWS + k];
        dp[q * 128 + k] = a;
    }
    __syncthreads();
    {
        const float* dp = U + 2688;
        const size_t BM = (size_t)Bsz * 640;
        const size_t BK = (size_t)Bsz * 128;
        if (tid < 128) {
            int k = tid;
            float p  = xs[k];
            float nu = xs[128 + k];
            float xg = xs[256 + k];
            float xv = xs[384 + k];
            float s4 = xs[512 + k];
            float f5 = 1.f - 1.f / ((1.f + xg) * (1.f + xg)) - xv;
            float f6 = sqrtf(xv) - s4;
            float dacc = dp[k] + dp[128 + k];
            float top  = p * HWs[k * HWS + k];
            float down = dacc - top + 1.f;
            out[BM +            (size_t)b * 128 + k] = f5;
            out[BM +     BK +   (size_t)b * 128 + k] = f6;
            out[BM + 2 * BK +   (size_t)b * 128 + k] = top - down * xg;
            out[BM + 3 * BK +   (size_t)b * 128 + k] = nu * down - top;
        }
    }
}

extern "C" void kernel_launch(void* const* d_in, const int* in_sizes, int n_in,
                              void* d_out, int out_size) {
    const float* HW    = (const float*)d_in[2];
    const float* x0    = (const float*)d_in[3];
    const float* nu3   = (const float*)d_in[4];
    const float* tg    = (const float*)d_in[5];
    const float* g1W0a = (const float*)d_in[12];
    const float* g1W1a = (const float*)d_in[13];
    const float* g1W0b = (const float*)d_in[14];
    const float* g1W1b = (const float*)d_in[15];
    const float* g2W0a = (const float*)d_in[16];
    const float* g2W1a = (const float*)d_in[17];
    const float* g2W0b = (const float*)d_in[18];
    const float* g2W1b = (const float*)d_in[19];

    cudaFuncSetAttribute(unfold_pocs_kernel,
                         cudaFuncAttributeMaxDynamicSharedMemorySize, SMEM_BYTES);

    unfold_pocs_kernel<<<Bsz, NTHREADS, SMEM_BYTES>>>(
        HW, x0, nu3, tg,
        g1W0a, g1W1a, g1W0b, g1W1b,
        g2W0a, g2W1a, g2W0b, g2W1b,
        (float*)d_out);
}

// round 12
// speedup vs baseline: 1.0050x; 1.0050x over previous
#include <cuda_runtime.h>
#include <math.h>
#include <stdint.h>

#define Bsz 2048
#define NTHREADS 256
#define HWS 132

typedef unsigned long long ull;

// ---- smem layout (float offsets) ----
#define O_HW   0        // 16896 : HW row-major stride 132
#define O_U    16896    // 9216 union region:
                        //  phase0/1: WBF (W64 frag) 8192 @ +0 ; X1t frag 1024 @ +8192
                        //  GNN1 : scrZ (Z1, stride 33) 4224 @ +0 ; Wct frag 512 @ +5376 ;
                        //          part 512 @ +5888
                        //  ph2/3: VBF frag 4096 @ +0 ; z2 [k][36] 4608 @ +4096
                        //  ph4/5: P0 640 @ +0 ; P5 1280 @ +640 ; dacc 256 @ +1920
#define O_XS   26112    // 640
#define O_SX1  26752    // 640 (SX1, later G)
#define O_SW   27392    // 1088
#define O_CC   28480    // 128
#define O_RED  28608    // 64
#define SMEM_FLOATS 28672
#define SMEM_BYTES (SMEM_FLOATS * 4)   // 114688 B -> 2 CTAs/SM

__device__ __forceinline__ ull dup2(float x) {
    ull r; asm("mov.b64 %0, {%1, %1};" : "=l"(r) : "f"(x)); return r;
}
#define FMA2(acc, a, b) asm("fma.rn.f32x2 %0, %1, %2, %0;" : "+l"(acc) : "l"(a), "l"(b))
__device__ __forceinline__ float hadd2(ull v) {
    float lo, hi; asm("mov.b64 {%0, %1}, %2;" : "=f"(lo), "=f"(hi) : "l"(v)); return lo + hi;
}
__device__ __forceinline__ void mma_tf32(float* c, const uint32_t* a, uint32_t b0, uint32_t b1) {
    asm volatile(
        "mma.sync.aligned.m16n8k8.row.col.f32.tf32.tf32.f32 "
        "{%0,%1,%2,%3}, {%4,%5,%6,%7}, {%8,%9}, {%0,%1,%2,%3};"
        : "+f"(c[0]), "+f"(c[1]), "+f"(c[2]), "+f"(c[3])
        : "r"(a[0]), "r"(a[1]), "r"(a[2]), "r"(a[3]), "r"(b0), "r"(b1));
}

__global__ __launch_bounds__(NTHREADS, 2)
void unfold_pocs_kernel(const float* __restrict__ gHW, const float* __restrict__ gx0,
                        const float* __restrict__ gnu3, const float* __restrict__ gtg,
                        const float* __restrict__ g1W0a, const float* __restrict__ g1W1a,
                        const float* __restrict__ g1W0b, const float* __restrict__ g1W1b,
                        const float* __restrict__ g2W0a, const float* __restrict__ g2W1a,
                        const float* __restrict__ g2W0b, const float* __restrict__ g2W1b,
                        float* __restrict__ out) {
    extern __shared__ float sm[];
    const int b = blockIdx.x;
    const int tid = threadIdx.x;
    const int wid = tid >> 5;
    const int lid = tid & 31;
    const int lr = lid >> 2;   // 0..7
    const int lc = lid & 3;    // 0..3

    float* HWs = sm + O_HW;
    float* U   = sm + O_U;
    float* xs  = sm + O_XS;
    float* sx1 = sm + O_SX1;
    float* sw  = sm + O_SW;
    float* cC  = sm + O_CC;
    float* red = sm + O_RED;

    const float* hwg = gHW + (size_t)b * (128 * 128);

    // ================= Phase 0: loads =================
    for (int o = tid; o < 4096; o += NTHREADS) {
        float4 v = *(const float4*)(hwg + o * 4);
        int w = o * 4;
        int row = w >> 7, col = w & 127;
        *(float4*)&HWs[row * HWS + col] = v;
    }
    for (int o = tid; o < 160; o += NTHREADS)
        *(float4*)&xs[o * 4] = *(const float4*)(gx0 + (size_t)b * 640 + o * 4);
    // W64 fragment-ordered into U+0 (vectorized gmem loads)
    {
        float* WBF = U;
        for (int o = tid; o < 1024; o += NTHREADS) {
            int k = o >> 3, h4 = (o & 7) * 4;
            float4 v0 = *(const float4*)&g2W0a[k * 32 + h4];
            float4 v1 = *(const float4*)&g2W1a[k * 32 + h4];
            int basek = (k >> 4) * 8;
            int comp  = (k >> 2) & 3;
            int l0    = (((h4 & 7) * 4 + (k & 3)) << 2) + comp;
            int c0 = (basek + (h4 >> 3)) << 7;
            int c1 = (basek + 4 + (h4 >> 3)) << 7;
            WBF[c0 + l0]      = v0.x;
            WBF[c0 + l0 + 16] = v0.y;
            WBF[c0 + l0 + 32] = v0.z;
            WBF[c0 + l0 + 48] = v0.w;
            WBF[c1 + l0]      = v1.x;
            WBF[c1 + l0 + 16] = v1.y;
            WBF[c1 + l0 + 32] = v1.z;
            WBF[c1 + l0 + 48] = v1.w;
        }
    }
    // X1t frag (N=8) into U+8192, read straight from gmem
    {
        float* X1t = U + 8192;
        const float* gx = gx0 + (size_t)b * 640;
        for (int o = tid; o < 1024; o += NTHREADS) {
            int k = o >> 3, f = o & 7;
            float v = (f < 5) ? gx[f * 128 + k] : 0.f;
            int pos = ((k >> 4) << 7) | ((f * 4 + (k & 3)) << 2) | ((k >> 2) & 3);
            X1t[pos] = v;
        }
    }
    for (int o = tid; o < 160; o += NTHREADS) sw[o]       = g1W0a[o];
    for (int o = tid; o < 160; o += NTHREADS) sw[160 + o] = g1W1a[o];
    for (int o = tid; o < 64;  o += NTHREADS) sw[320 + o] = g1W0b[o];
    for (int o = tid; o < 64;  o += NTHREADS) sw[384 + o] = g1W1b[o];
    for (int o = tid; o < 160; o += NTHREADS) sw[448 + o] = g2W0a[128 * 32 + o];
    for (int o = tid; o < 160; o += NTHREADS) sw[608 + o] = g2W1a[128 * 32 + o];
    for (int o = tid; o < 160; o += NTHREADS) {
        int f = o >> 5, h = o & 31;
        sw[768 + f * 32 + h] = g2W0b[h * 5 + f];
        sw[928 + f * 32 + h] = g2W1b[h * 5 + f];
    }
    __syncthreads();

    float acc[8][4];     // T fragments, then U0 in acc[0..3]
    float acc2[4][4];    // phase1: acc2[0] = SX1 tile ; later HW@V fragments
    const int m0 = wid * 16;

    // ================= Phase 1: [T | SX1] = HW @ [W64 | X1] via HMMA tf32 =================
    {
        const float* WBF = U;
        const float* X1t = U + 8192;
#pragma unroll
        for (int nt = 0; nt < 8; nt++)
#pragma unroll
            for (int c = 0; c < 4; c++) acc[nt][c] = 0.f;
#pragma unroll
        for (int c = 0; c < 4; c++) acc2[0][c] = 0.f;
#pragma unroll
        for (int kc = 0; kc < 8; kc++) {
            const int k0 = kc * 16;
            uint32_t a0[4], a1[4];
            a0[0] = __float_as_uint(HWs[(m0 + lr)     * HWS + k0 + lc]);
            a0[1] = __float_as_uint(HWs[(m0 + lr + 8) * HWS + k0 + lc]);
            a0[2] = __float_as_uint(HWs[(m0 + lr)     * HWS + k0 + lc + 4]);
            a0[3] = __float_as_uint(HWs[(m0 + lr + 8) * HWS + k0 + lc + 4]);
            a1[0] = __float_as_uint(HWs[(m0 + lr)     * HWS + k0 + 8 + lc]);
            a1[1] = __float_as_uint(HWs[(m0 + lr + 8) * HWS + k0 + 8 + lc]);
            a1[2] = __float_as_uint(HWs[(m0 + lr)     * HWS + k0 + 12 + lc]);
            a1[3] = __float_as_uint(HWs[(m0 + lr + 8) * HWS + k0 + 12 + lc]);
#pragma unroll
            for (int nt = 0; nt < 8; nt++) {
                float4 bv = *(const float4*)&WBF[((kc << 3) + nt) << 7 | (lid << 2)];
                mma_tf32(acc[nt], a0, __float_as_uint(bv.x), __float_as_uint(bv.y));
                mma_tf32(acc[nt], a1, __float_as_uint(bv.z), __float_as_uint(bv.w));
            }
            {
                float4 bv = *(const float4*)&X1t[(kc << 7) | (lid << 2)];
                mma_tf32(acc2[0], a0, __float_as_uint(bv.x), __float_as_uint(bv.y));
                mma_tf32(acc2[0], a1, __float_as_uint(bv.z), __float_as_uint(bv.w));
            }
        }
        int f0 = 2 * lc, f1 = 2 * lc + 1;
        if (f0 < 5) {
            sx1[f0 * 128 + m0 + lr]     = acc2[0][0];
            sx1[f0 * 128 + m0 + lr + 8] = acc2[0][2];
        }
        if (f1 < 5) {
            sx1[f1 * 128 + m0 + lr]     = acc2[0][1];
            sx1[f1 * 128 + m0 + lr + 8] = acc2[0][3];
        }
    }
    __syncthreads();   // WBF/X1t dead; sx1 = SX1 ready

    // ================= GNN1 (HMMA) =================
    {
        float* scrZ = U;          // Z1, stride 33
        float* Wct  = U + 5376;   // cat-weights frag (k=16, N=32)
        float* part = U + 5888;

        for (int o = tid; o < 512; o += NTHREADS) {
            int h = o >> 4, k = o & 15;
            float v = (k < 5) ? sw[k * 32 + h] : (k < 10 ? sw[160 + (k - 5) * 32 + h] : 0.f);
            int pos = ((h >> 3) << 7) | (((h & 7) * 4 + (k & 3)) << 2) | ((k >> 2) & 3);
            Wct[pos] = v;
        }
        if (tid < 128) {
            float a = 0.f;
#pragma unroll 4
            for (int i = 0; i < 128; i++) a += HWs[i * HWS + tid];
            cC[tid] = a * (1.f / 128.f);
        }
        __syncthreads();

        // Z1 = relu(cat @ Wct) via HMMA, cat = [X1 | SX1] (k=10 pad 16)
        {
            const int row0 = m0 + lr, row1 = m0 + lr + 8;
            uint32_t a0[4], a1[4];
            a0[0] = __float_as_uint(xs[lc * 128 + row0]);
            a0[1] = __float_as_uint(xs[lc * 128 + row1]);
            a0[2] = __float_as_uint((lc == 0) ? xs[4 * 128 + row0] : sx1[(lc - 1) * 128 + row0]);
            a0[3] = __float_as_uint((lc == 0) ? xs[4 * 128 + row1] : sx1[(lc - 1) * 128 + row1]);
            a1[0] = (lc < 2) ? __float_as_uint(sx1[(lc + 3) * 128 + row0]) : 0u;
            a1[1] = (lc < 2) ? __float_as_uint(sx1[(lc + 3) * 128 + row1]) : 0u;
            a1[2] = 0u;
            a1[3] = 0u;
            float cz[4][4];
#pragma unroll
            for (int nt = 0; nt < 4; nt++) {
#pragma unroll
                for (int c = 0; c < 4; c++) cz[nt][c] = 0.f;
                float4 bv = *(const float4*)&Wct[(nt << 7) | (lid << 2)];
                mma_tf32(cz[nt], a0, __float_as_uint(bv.x), __float_as_uint(bv.y));
                mma_tf32(cz[nt], a1, __float_as_uint(bv.z), __float_as_uint(bv.w));
            }
#pragma unroll
            for (int nt = 0; nt < 4; nt++) {
                const int h0 = nt * 8 + 2 * lc;
                scrZ[row0 * 33 + h0]     = fmaxf(cz[nt][0], 0.f);
                scrZ[row0 * 33 + h0 + 1] = fmaxf(cz[nt][1], 0.f);
                scrZ[row1 * 33 + h0]     = fmaxf(cz[nt][2], 0.f);
                scrZ[row1 * 33 + h0 + 1] = fmaxf(cz[nt][3], 0.f);
            }
        }
        __syncthreads();

        {
            const int h = tid & 31, q = tid >> 5;
            float m = 0.f, cz = 0.f;
#pragma unroll 4
            for (int k = q * 16; k < q * 16 + 16; k++) {
                float zv = scrZ[k * 33 + h];
                m += zv;
                cz += cC[k] * zv;
            }
            part[q * 32 + h] = m;
            part[256 + q * 32 + h] = cz;
        }
        __syncthreads();
        if (tid < 32) {
            float m = 0.f, cz = 0.f;
#pragma unroll
            for (int q = 0; q < 8; q++) {
                m  += part[q * 32 + tid];
                cz += part[256 + q * 32 + tid];
            }
            red[tid] = m * (1.f / 128.f);
            red[32 + tid] = cz;
        }
        __syncthreads();
        if (tid < 2) {
            const float* w0b = sw + 320;
            const float* w1b = sw + 384;
            float a = 0.f;
#pragma unroll 8
            for (int h = 0; h < 32; h++)
                a += red[h] * w0b[h * 2 + tid] + red[32 + h] * w1b[h * 2 + tid];
            red[62 + tid] = fmaxf(a, 0.f);   // lbd
        }
        __syncthreads();
        if (tid < 128) {
            float l0 = red[62], l1 = red[63];
            float s1v = xs[128 + tid];
            xs[128 + tid] = s1v - l0 * ((1.0f / 128.f) / (1.f + s1v));
            xs[512 + tid] += l1 * ((1.0f / 128.f) * 0.1f);
        }
    }
    __syncthreads();   // xs final

    // ================= Phase 2+3: U0 in regs, V frag, HMMA HW@V, z2 =================
    {
        float* VBF = U;            // V fragment order (N=32 -> 4 n-tiles)
        float* z2s = U + 4096;     // [k][36]
        const float* w0bot = sw + 448;
        const float* w1bot = sw + 608;
        float xr[2][5];
#pragma unroll
        for (int f = 0; f < 5; f++) {
            xr[0][f] = xs[f * 128 + m0 + lr];
            xr[1][f] = xs[f * 128 + m0 + lr + 8];
        }
        const int lr3 = lr & 3, lrh = lr >> 2;
#pragma unroll
        for (int nt = 0; nt < 8; nt++) {
            const bool isU = nt < 4;
            const float* wb = isU ? w0bot : w1bot;
            const int hb = (isU ? nt : nt - 4) * 8 + 2 * lc;
            float r00 = acc[nt][0], r01 = acc[nt][1];
            float r10 = acc[nt][2], r11 = acc[nt][3];
#pragma unroll
            for (int f = 0; f < 5; f++) {
                float w0 = wb[f * 32 + hb], w1 = wb[f * 32 + hb + 1];
                r00 += xr[0][f] * w0; r01 += xr[0][f] * w1;
                r10 += xr[1][f] * w0; r11 += xr[1][f] * w1;
            }
            if (isU) {
                acc[nt][0] = r00; acc[nt][1] = r01; acc[nt][2] = r10; acc[nt][3] = r11;
            } else {
                const int ch = ((wid * 4) + (nt - 4)) << 7;
                const int p0 = ch | (((2 * lc) * 4 + lr3) << 2);
                const int p1 = ch | (((2 * lc + 1) * 4 + lr3) << 2);
                VBF[p0 + lrh]     = r00;
                VBF[p1 + lrh]     = r01;
                VBF[p0 + 2 + lrh] = r10;
                VBF[p1 + 2 + lrh] = r11;
            }
        }
        __syncthreads();   // V fully written

#pragma unroll
        for (int nt = 0; nt < 4; nt++)
#pragma unroll
            for (int c = 0; c < 4; c++) acc2[nt][c] = 0.f;
#pragma unroll
        for (int kc = 0; kc < 8; kc++) {
            const int k0 = kc * 16;
            uint32_t a0[4], a1[4];
            a0[0] = __float_as_uint(HWs[(m0 + lr)     * HWS + k0 + lc]);
            a0[1] = __float_as_uint(HWs[(m0 + lr + 8) * HWS + k0 + lc]);
            a0[2] = __float_as_uint(HWs[(m0 + lr)     * HWS + k0 + lc + 4]);
            a0[3] = __float_as_uint(HWs[(m0 + lr + 8) * HWS + k0 + lc + 4]);
            a1[0] = __float_as_uint(HWs[(m0 + lr)     * HWS + k0 + 8 + lc]);
            a1[1] = __float_as_uint(HWs[(m0 + lr + 8) * HWS + k0 + 8 + lc]);
            a1[2] = __float_as_uint(HWs[(m0 + lr)     * HWS + k0 + 12 + lc]);
            a1[3] = __float_as_uint(HWs[(m0 + lr + 8) * HWS + k0 + 12 + lc]);
#pragma unroll
            for (int nt = 0; nt < 4; nt++) {
                float4 bv = *(const float4*)&VBF[((kc << 2) + nt) << 7 | (lid << 2)];
                mma_tf32(acc2[nt], a0, __float_as_uint(bv.x), __float_as_uint(bv.y));
                mma_tf32(acc2[nt], a1, __float_as_uint(bv.z), __float_as_uint(bv.w));
            }
        }
#pragma unroll
        for (int nt = 0; nt < 4; nt++) {
            const int hb = nt * 8 + 2 * lc;
            *(float2*)&z2s[(m0 + lr) * 36 + hb] =
                make_float2(fmaxf(acc[nt][0] + acc2[nt][0], 0.f),
                            fmaxf(acc[nt][1] + acc2[nt][1], 0.f));
            *(float2*)&z2s[(m0 + lr + 8) * 36 + hb] =
                make_float2(fmaxf(acc[nt][2] + acc2[nt][2], 0.f),
                            fmaxf(acc[nt][3] + acc2[nt][3], 0.f));
        }
    }
    __syncthreads();

    // ================= Phase 4: G = Z2@W1b (->sx1), P0 = Z2@W0b (->U+0) =================
    {
        const float* z2s = U + 4096;
        float* P0 = U;
        for (int o = tid; o < 640; o += NTHREADS) {
            int k = o & 127, f = o >> 7;
            const float* zr  = &z2s[k * 36];
            const float* wp0 = &sw[768 + f * 32];
            const float* wp1 = &sw[928 + f * 32];
            ull g2a = 0ull, p2a = 0ull;
#pragma unroll
            for (int h = 0; h < 32; h += 4) {
                ulonglong2 zv  = *(const ulonglong2*)&zr[h];
                ulonglong2 w1v = *(const ulonglong2*)&wp1[h];
                ulonglong2 w0v = *(const ulonglong2*)&wp0[h];
                FMA2(g2a, zv.x, w1v.x);
                FMA2(g2a, zv.y, w1v.y);
                FMA2(p2a, zv.x, w0v.x);
                FMA2(p2a, zv.y, w0v.y);
            }
            sx1[f * 128 + k] = hadd2(g2a);
            P0[o] = hadd2(p2a);
        }
    }
    __syncthreads();

    // ================= Phase 5: partials of HW@G (j-split 2) =================
    {
        float* P5 = U + 640;
        const int k = tid & 127, q = tid >> 7;
        const int jb = 64 * q;
        const float* hr = &HWs[k * HWS + jb];
        ull a2[5] = {0ull, 0ull, 0ull, 0ull, 0ull};
#pragma unroll 4
        for (int j = 0; j < 64; j += 4) {
            ulonglong2 h2v = *(const ulonglong2*)&hr[j];
#pragma unroll
            for (int f = 0; f < 5; f++) {
                ulonglong2 gv = *(const ulonglong2*)&sx1[f * 128 + jb + j];
                FMA2(a2[f], h2v.x, gv.x);
                FMA2(a2[f], h2v.y, gv.y);
            }
        }
#pragma unroll
        for (int f = 0; f < 5; f++)
            P5[q * 640 + f * 128 + k] = hadd2(a2[f]);
    }
    __syncthreads();

    // ===== x update + fused band-0 reduction =====
    {
        float bs = 0.f;
        for (int o = tid; o < 640; o += NTHREADS) {
            float v = xs[o] + U[o] + U[640 + o] + U[1280 + o];
            xs[o] = v;
            if (o < 128) bs = v;
        }
        if (tid < 128) {
#pragma unroll
            for (int m = 16; m > 0; m >>= 1) bs += __shfl_xor_sync(0xffffffffu, bs, m);
            if ((tid & 31) == 0) red[8 + (tid >> 5)] = bs;
        }
    }
    __syncthreads();

    // ===== projection + band clamps + output x (fused) =====
    {
        float fproj = red[8] + red[9] + red[10] + red[11] - 10.0f;
        float nu3 = gnu3[0], tg = gtg[0];
        float Vnu = 1.f - 1.f / ((1.f + nu3) * (1.f + nu3));
        float Vg  = 1.f - 1.f / ((1.f + tg) * (1.f + tg));
        float* outx = out + (size_t)b * 640;
        for (int m = tid; m < 640; m += NTHREADS) {
            float v = xs[m];
            int band = m >> 7;
            if (band == 0 && fproj > 0.f) v -= fproj * (1.f / 128.f);
            v = fmaxf(v, band == 1 ? nu3 : 0.f);
            if (band == 2) v = fminf(v, tg);
            if (band == 3) v = fminf(fmaxf(v, Vnu), Vg);
            xs[m] = v;
            outx[m] = v;
        }
    }
    __syncthreads();

    // ================= dacc partials + final outputs =================
    {
        float* dp = U + 1920;
        const int k = tid & 127, q = tid >> 7;
        float a = 0.f;
#pragma unroll 8
        for (int i = 64 * q; i < 64 * q + 64; i++)
            a += xs[i] * HWs[i * HWS + k];
        dp[q * 128 + k] = a;
    }
    __syncthreads();
    {
        const float* dp = U + 1920;
        const size_t BM = (size_t)Bsz * 640;
        const size_t BK = (size_t)Bsz * 128;
        if (tid < 128) {
            int k = tid;
            float p  = xs[k];
            float nu = xs[128 + k];
            float xg = xs[256 + k];
            float xv = xs[384 + k];
            float s4 = xs[512 + k];
            float f5 = 1.f - 1.f / ((1.f + xg) * (1.f + xg)) - xv;
            float f6 = sqrtf(xv) - s4;
            float dacc = dp[k] + dp[128 + k];
            float top  = p * HWs[k * HWS + k];
            float down = dacc - top + 1.f;
            out[BM +            (size_t)b * 128 + k] = f5;
            out[BM +     BK +   (size_t)b * 128 + k] = f6;
            out[BM + 2 * BK +   (size_t)b * 128 + k] = top - down * xg;
            out[BM + 3 * BK +   (size_t)b * 128 + k] = nu * down - top;
        }
    }
}

extern "C" void kernel_launch(void* const* d_in, const int* in_sizes, int n_in,
                              void* d_out, int out_size) {
    const float* HW    = (const float*)d_in[2];
    const float* x0    = (const float*)d_in[3];
    const float* nu3   = (const float*)d_in[4];
    const float* tg    = (const float*)d_in[5];
    const float* g1W0a = (const float*)d_in[12];
    const float* g1W1a = (const float*)d_in[13];
    const float* g1W0b = (const float*)d_in[14];
    const float* g1W1b = (const float*)d_in[15];
    const float* g2W0a = (const float*)d_in[16];
    const float* g2W1a = (const float*)d_in[17];
    const float* g2W0b = (const float*)d_in[18];
    const float* g2W1b = (const float*)d_in[19];

    cudaFuncSetAttribute(unfold_pocs_kernel,
                         cudaFuncAttributeMaxDynamicSharedMemorySize, SMEM_BYTES);

    unfold_pocs_kernel<<<Bsz, NTHREADS, SMEM_BYTES>>>(
        HW, x0, nu3, tg,
        g1W0a, g1W1a, g1W0b, g1W1b,
        g2W0a, g2W1a, g2W0b, g2W1b,
        (float*)d_out);
}

// round 13
// speedup vs baseline: 1.0541x; 1.0488x over previous
#include <cuda_runtime.h>
#include <math.h>
#include <stdint.h>

#define Bsz 2048
#define NTHREADS 256
#define HWS 132

typedef unsigned long long ull;

// ---- smem layout (float offsets) ----
#define O_HW   0        // 16896 : HW row-major stride 132
#define O_U    16896    // 9216 union region:
                        //  phase0/1: WBF (W64 frag) 8192 @ +0 ; X1t frag 1024 @ +8192
                        //  GNN1 : Wct frag 512 @ +5376 ; part 512 @ +5888 ; cpart 256 @ +6400
                        //  ph2/3: VBF frag 4096 @ +0 ; z2 [k][36] 4608 @ +4096
                        //  ph4/5: P0 640 @ +0 ; P5 1280 @ +640 ; dacc 256 @ +1920
#define O_XS   26112    // 640
#define O_SX1  26752    // 640 (SX1, later G)
#define O_SW   27392    // 1088
#define O_CC   28480    // 128 (unused spare)
#define O_RED  28608    // 64
#define SMEM_FLOATS 28672
#define SMEM_BYTES (SMEM_FLOATS * 4)   // 114688 B -> 2 CTAs/SM

__device__ __forceinline__ ull dup2(float x) {
    ull r; asm("mov.b64 %0, {%1, %1};" : "=l"(r) : "f"(x)); return r;
}
#define FMA2(acc, a, b) asm("fma.rn.f32x2 %0, %1, %2, %0;" : "+l"(acc) : "l"(a), "l"(b))
__device__ __forceinline__ float hadd2(ull v) {
    float lo, hi; asm("mov.b64 {%0, %1}, %2;" : "=f"(lo), "=f"(hi) : "l"(v)); return lo + hi;
}
__device__ __forceinline__ void mma_tf32(float* c, const uint32_t* a, uint32_t b0, uint32_t b1) {
    asm volatile(
        "mma.sync.aligned.m16n8k8.row.col.f32.tf32.tf32.f32 "
        "{%0,%1,%2,%3}, {%4,%5,%6,%7}, {%8,%9}, {%0,%1,%2,%3};"
        : "+f"(c[0]), "+f"(c[1]), "+f"(c[2]), "+f"(c[3])
        : "r"(a[0]), "r"(a[1]), "r"(a[2]), "r"(a[3]), "r"(b0), "r"(b1));
}

__global__ __launch_bounds__(NTHREADS, 2)
void unfold_pocs_kernel(const float* __restrict__ gHW, const float* __restrict__ gx0,
                        const float* __restrict__ gnu3, const float* __restrict__ gtg,
                        const float* __restrict__ g1W0a, const float* __restrict__ g1W1a,
                        const float* __restrict__ g1W0b, const float* __restrict__ g1W1b,
                        const float* __restrict__ g2W0a, const float* __restrict__ g2W1a,
                        const float* __restrict__ g2W0b, const float* __restrict__ g2W1b,
                        float* __restrict__ out) {
    extern __shared__ float sm[];
    const int b = blockIdx.x;
    const int tid = threadIdx.x;
    const int wid = tid >> 5;
    const int lid = tid & 31;
    const int lr = lid >> 2;   // 0..7
    const int lc = lid & 3;    // 0..3

    float* HWs = sm + O_HW;
    float* U   = sm + O_U;
    float* xs  = sm + O_XS;
    float* sx1 = sm + O_SX1;
    float* sw  = sm + O_SW;
    float* red = sm + O_RED;

    const float* hwg = gHW + (size_t)b * (128 * 128);

    // ================= Phase 0: loads =================
    for (int o = tid; o < 4096; o += NTHREADS) {
        float4 v = *(const float4*)(hwg + o * 4);
        int w = o * 4;
        int row = w >> 7, col = w & 127;
        *(float4*)&HWs[row * HWS + col] = v;
    }
    for (int o = tid; o < 160; o += NTHREADS)
        *(float4*)&xs[o * 4] = *(const float4*)(gx0 + (size_t)b * 640 + o * 4);
    // W64 fragment build: conflict-free float4 STS (chunk-lane identity)
    {
        float* WBF = U;
        for (int o = tid; o < 2048; o += NTHREADS) {
            int chunk = o >> 5, lane = o & 31;
            int kc = chunk >> 3, nt = chunk & 7;
            int k3 = lane & 3, hq = lane >> 2;
            const float* src = (nt < 4) ? (g2W0a + (nt * 8 + hq)) : (g2W1a + ((nt - 4) * 8 + hq));
            int kbase = kc * 16 + k3;
            float4 v;
            v.x = src[(kbase)      * 32];
            v.y = src[(kbase + 4)  * 32];
            v.z = src[(kbase + 8)  * 32];
            v.w = src[(kbase + 12) * 32];
            *(float4*)&WBF[(chunk << 7) + (lane << 2)] = v;
        }
    }
    // X1t frag build (N=8): conflict-free float4 STS
    {
        float* X1t = U + 8192;
        const float* gx = gx0 + (size_t)b * 640;
        for (int o = tid; o < 256; o += NTHREADS) {
            int chunk = o >> 5, lane = o & 31;     // chunk = kc
            int k3 = lane & 3, f = lane >> 2;
            int kbase = chunk * 16 + k3;
            float4 v = make_float4(0.f, 0.f, 0.f, 0.f);
            if (f < 5) {
                const float* src = gx + f * 128;
                v.x = src[kbase];
                v.y = src[kbase + 4];
                v.z = src[kbase + 8];
                v.w = src[kbase + 12];
            }
            *(float4*)&X1t[(chunk << 7) + (lane << 2)] = v;
        }
    }
    for (int o = tid; o < 160; o += NTHREADS) sw[o]       = g1W0a[o];
    for (int o = tid; o < 160; o += NTHREADS) sw[160 + o] = g1W1a[o];
    for (int o = tid; o < 64;  o += NTHREADS) sw[320 + o] = g1W0b[o];
    for (int o = tid; o < 64;  o += NTHREADS) sw[384 + o] = g1W1b[o];
    for (int o = tid; o < 160; o += NTHREADS) sw[448 + o] = g2W0a[128 * 32 + o];
    for (int o = tid; o < 160; o += NTHREADS) sw[608 + o] = g2W1a[128 * 32 + o];
    for (int o = tid; o < 160; o += NTHREADS) {
        int f = o >> 5, h = o & 31;
        sw[768 + f * 32 + h] = g2W0b[h * 5 + f];
        sw[928 + f * 32 + h] = g2W1b[h * 5 + f];
    }
    __syncthreads();

    float acc[8][4];     // T fragments, then U0 in acc[0..3]
    float acc2[4][4];    // phase1: acc2[0] = SX1 tile ; later HW@V fragments
    const int m0 = wid * 16;

    // ================= Phase 1: [T | SX1] = HW @ [W64 | X1] via HMMA tf32 =================
    {
        const float* WBF = U;
        const float* X1t = U + 8192;
#pragma unroll
        for (int nt = 0; nt < 8; nt++)
#pragma unroll
            for (int c = 0; c < 4; c++) acc[nt][c] = 0.f;
#pragma unroll
        for (int c = 0; c < 4; c++) acc2[0][c] = 0.f;
#pragma unroll
        for (int kc = 0; kc < 8; kc++) {
            const int k0 = kc * 16;
            uint32_t a0[4], a1[4];
            a0[0] = __float_as_uint(HWs[(m0 + lr)     * HWS + k0 + lc]);
            a0[1] = __float_as_uint(HWs[(m0 + lr + 8) * HWS + k0 + lc]);
            a0[2] = __float_as_uint(HWs[(m0 + lr)     * HWS + k0 + lc + 4]);
            a0[3] = __float_as_uint(HWs[(m0 + lr + 8) * HWS + k0 + lc + 4]);
            a1[0] = __float_as_uint(HWs[(m0 + lr)     * HWS + k0 + 8 + lc]);
            a1[1] = __float_as_uint(HWs[(m0 + lr + 8) * HWS + k0 + 8 + lc]);
            a1[2] = __float_as_uint(HWs[(m0 + lr)     * HWS + k0 + 12 + lc]);
            a1[3] = __float_as_uint(HWs[(m0 + lr + 8) * HWS + k0 + 12 + lc]);
#pragma unroll
            for (int nt = 0; nt < 8; nt++) {
                float4 bv = *(const float4*)&WBF[((kc << 3) + nt) << 7 | (lid << 2)];
                mma_tf32(acc[nt], a0, __float_as_uint(bv.x), __float_as_uint(bv.y));
                mma_tf32(acc[nt], a1, __float_as_uint(bv.z), __float_as_uint(bv.w));
            }
            {
                float4 bv = *(const float4*)&X1t[(kc << 7) | (lid << 2)];
                mma_tf32(acc2[0], a0, __float_as_uint(bv.x), __float_as_uint(bv.y));
                mma_tf32(acc2[0], a1, __float_as_uint(bv.z), __float_as_uint(bv.w));
            }
        }
        int f0 = 2 * lc, f1 = 2 * lc + 1;
        if (f0 < 5) {
            sx1[f0 * 128 + m0 + lr]     = acc2[0][0];
            sx1[f0 * 128 + m0 + lr + 8] = acc2[0][2];
        }
        if (f1 < 5) {
            sx1[f1 * 128 + m0 + lr]     = acc2[0][1];
            sx1[f1 * 128 + m0 + lr + 8] = acc2[0][3];
        }
    }
    __syncthreads();   // WBF/X1t dead; sx1 = SX1 ready

    // ================= GNN1 (HMMA, Z1 reduced in registers) =================
    {
        float* Wct   = U + 5376;   // cat-weights frag (k=16, N=32)
        float* part  = U + 5888;   // 512: warp partials (sums | wsums)
        float* cpart = U + 6400;   // 256: colmean partials

        // Wct build: conflict-free float4 STS
        for (int o = tid; o < 128; o += NTHREADS) {
            int chunk = o >> 5, lane = o & 31;   // chunk = h>>3 (0..3)
            int k3 = lane & 3, hq = lane >> 2;
            int h = chunk * 8 + hq;
            float4 v;
            // k = k3 + 4c ; k<5 -> W0a[k][h], k<10 -> W1a[k-5][h], else 0
#pragma unroll
            for (int c = 0; c < 4; c++) {
                int k = k3 + 4 * c;
                float x = (k < 5) ? sw[k * 32 + h] : (k < 10 ? sw[160 + (k - 5) * 32 + h] : 0.f);
                ((float*)&v)[c] = x;
            }
            *(float4*)&Wct[(chunk << 7) + (lane << 2)] = v;
        }
        // colmean partials, all 256 threads (i-split 2)
        {
            int col = tid & 127, half = tid >> 7;
            float a = 0.f;
#pragma unroll 4
            for (int i = 64 * half; i < 64 * half + 64; i++)
                a += HWs[i * HWS + col];
            cpart[half * 128 + col] = a;
        }
        __syncthreads();

        // Z1 = relu(cat @ Wct) via HMMA; reduce rows in registers
        {
            const int row0 = m0 + lr, row1 = row0 + 8;
            float cr0 = (cpart[row0] + cpart[128 + row0]) * (1.f / 128.f);
            float cr1 = (cpart[row1] + cpart[128 + row1]) * (1.f / 128.f);
            uint32_t a0[4], a1[4];
            a0[0] = __float_as_uint(xs[lc * 128 + row0]);
            a0[1] = __float_as_uint(xs[lc * 128 + row1]);
            a0[2] = __float_as_uint((lc == 0) ? xs[4 * 128 + row0] : sx1[(lc - 1) * 128 + row0]);
            a0[3] = __float_as_uint((lc == 0) ? xs[4 * 128 + row1] : sx1[(lc - 1) * 128 + row1]);
            a1[0] = (lc < 2) ? __float_as_uint(sx1[(lc + 3) * 128 + row0]) : 0u;
            a1[1] = (lc < 2) ? __float_as_uint(sx1[(lc + 3) * 128 + row1]) : 0u;
            a1[2] = 0u;
            a1[3] = 0u;
#pragma unroll
            for (int nt = 0; nt < 4; nt++) {
                float cz[4] = {0.f, 0.f, 0.f, 0.f};
                float4 bv = *(const float4*)&Wct[(nt << 7) | (lid << 2)];
                mma_tf32(cz, a0, __float_as_uint(bv.x), __float_as_uint(bv.y));
                mma_tf32(cz, a1, __float_as_uint(bv.z), __float_as_uint(bv.w));
                float r0 = fmaxf(cz[0], 0.f), r1 = fmaxf(cz[1], 0.f);
                float r2 = fmaxf(cz[2], 0.f), r3 = fmaxf(cz[3], 0.f);
                float s0 = r0 + r2, s1 = r1 + r3;
                float w0 = cr0 * r0 + cr1 * r2, w1 = cr0 * r1 + cr1 * r3;
#pragma unroll
                for (int msk = 4; msk <= 16; msk <<= 1) {
                    s0 += __shfl_xor_sync(0xffffffffu, s0, msk);
                    s1 += __shfl_xor_sync(0xffffffffu, s1, msk);
                    w0 += __shfl_xor_sync(0xffffffffu, w0, msk);
                    w1 += __shfl_xor_sync(0xffffffffu, w1, msk);
                }
                if (lr == 0) {
                    part[wid * 32 + nt * 8 + 2 * lc]           = s0;
                    part[wid * 32 + nt * 8 + 2 * lc + 1]       = s1;
                    part[256 + wid * 32 + nt * 8 + 2 * lc]     = w0;
                    part[256 + wid * 32 + nt * 8 + 2 * lc + 1] = w1;
                }
            }
        }
        __syncthreads();
        if (tid < 32) {
            float m = 0.f, cz = 0.f;
#pragma unroll
            for (int q = 0; q < 8; q++) {
                m  += part[q * 32 + tid];
                cz += part[256 + q * 32 + tid];
            }
            red[tid] = m * (1.f / 128.f);
            red[32 + tid] = cz;
        }
        __syncthreads();
        if (tid < 2) {
            const float* w0b = sw + 320;
            const float* w1b = sw + 384;
            float a = 0.f;
#pragma unroll 8
            for (int h = 0; h < 32; h++)
                a += red[h] * w0b[h * 2 + tid] + red[32 + h] * w1b[h * 2 + tid];
            red[62 + tid] = fmaxf(a, 0.f);   // lbd
        }
        __syncthreads();
        if (tid < 128) {
            float l0 = red[62], l1 = red[63];
            float s1v = xs[128 + tid];
            xs[128 + tid] = s1v - l0 * ((1.0f / 128.f) / (1.f + s1v));
            xs[512 + tid] += l1 * ((1.0f / 128.f) * 0.1f);
        }
    }
    __syncthreads();   // xs final

    // ================= Phase 2+3: U0 in regs, V frag, HMMA HW@V, z2 =================
    {
        float* VBF = U;            // V fragment order (N=32 -> 4 n-tiles)
        float* z2s = U + 4096;     // [k][36]
        const float* w0bot = sw + 448;
        const float* w1bot = sw + 608;
        float xr[2][5];
#pragma unroll
        for (int f = 0; f < 5; f++) {
            xr[0][f] = xs[f * 128 + m0 + lr];
            xr[1][f] = xs[f * 128 + m0 + lr + 8];
        }
        const int lr3 = lr & 3, lrh = lr >> 2;
#pragma unroll
        for (int nt = 0; nt < 8; nt++) {
            const bool isU = nt < 4;
            const float* wb = isU ? w0bot : w1bot;
            const int hb = (isU ? nt : nt - 4) * 8 + 2 * lc;
            float r00 = acc[nt][0], r01 = acc[nt][1];
            float r10 = acc[nt][2], r11 = acc[nt][3];
#pragma unroll
            for (int f = 0; f < 5; f++) {
                float w0 = wb[f * 32 + hb], w1 = wb[f * 32 + hb + 1];
                r00 += xr[0][f] * w0; r01 += xr[0][f] * w1;
                r10 += xr[1][f] * w0; r11 += xr[1][f] * w1;
            }
            if (isU) {
                acc[nt][0] = r00; acc[nt][1] = r01; acc[nt][2] = r10; acc[nt][3] = r11;
            } else {
                const int ch = ((wid * 4) + (nt - 4)) << 7;
                const int p0 = ch | (((2 * lc) * 4 + lr3) << 2);
                const int p1 = ch | (((2 * lc + 1) * 4 + lr3) << 2);
                VBF[p0 + lrh]     = r00;
                VBF[p1 + lrh]     = r01;
                VBF[p0 + 2 + lrh] = r10;
                VBF[p1 + 2 + lrh] = r11;
            }
        }
        __syncthreads();   // V fully written

#pragma unroll
        for (int nt = 0; nt < 4; nt++)
#pragma unroll
            for (int c = 0; c < 4; c++) acc2[nt][c] = 0.f;
#pragma unroll
        for (int kc = 0; kc < 8; kc++) {
            const int k0 = kc * 16;
            uint32_t a0[4], a1[4];
            a0[0] = __float_as_uint(HWs[(m0 + lr)     * HWS + k0 + lc]);
            a0[1] = __float_as_uint(HWs[(m0 + lr + 8) * HWS + k0 + lc]);
            a0[2] = __float_as_uint(HWs[(m0 + lr)     * HWS + k0 + lc + 4]);
            a0[3] = __float_as_uint(HWs[(m0 + lr + 8) * HWS + k0 + lc + 4]);
            a1[0] = __float_as_uint(HWs[(m0 + lr)     * HWS + k0 + 8 + lc]);
            a1[1] = __float_as_uint(HWs[(m0 + lr + 8) * HWS + k0 + 8 + lc]);
            a1[2] = __float_as_uint(HWs[(m0 + lr)     * HWS + k0 + 12 + lc]);
            a1[3] = __float_as_uint(HWs[(m0 + lr + 8) * HWS + k0 + 12 + lc]);
#pragma unroll
            for (int nt = 0; nt < 4; nt++) {
                float4 bv = *(const float4*)&VBF[((kc << 2) + nt) << 7 | (lid << 2)];
                mma_tf32(acc2[nt], a0, __float_as_uint(bv.x), __float_as_uint(bv.y));
                mma_tf32(acc2[nt], a1, __float_as_uint(bv.z), __float_as_uint(bv.w));
            }
        }
#pragma unroll
        for (int nt = 0; nt < 4; nt++) {
            const int hb = nt * 8 + 2 * lc;
            *(float2*)&z2s[(m0 + lr) * 36 + hb] =
                make_float2(fmaxf(acc[nt][0] + acc2[nt][0], 0.f),
                            fmaxf(acc[nt][1] + acc2[nt][1], 0.f));
            *(float2*)&z2s[(m0 + lr + 8) * 36 + hb] =
                make_float2(fmaxf(acc[nt][2] + acc2[nt][2], 0.f),
                            fmaxf(acc[nt][3] + acc2[nt][3], 0.f));
        }
    }
    __syncthreads();

    // ================= Phase 4: G = Z2@W1b (->sx1), P0 = Z2@W0b (->U+0) =================
    {
        const float* z2s = U + 4096;
        float* P0 = U;
        for (int o = tid; o < 640; o += NTHREADS) {
            int k = o & 127, f = o >> 7;
            const float* zr  = &z2s[k * 36];
            const float* wp0 = &sw[768 + f * 32];
            const float* wp1 = &sw[928 + f * 32];
            ull g2a = 0ull, p2a = 0ull;
#pragma unroll
            for (int h = 0; h < 32; h += 4) {
                ulonglong2 zv  = *(const ulonglong2*)&zr[h];
                ulonglong2 w1v = *(const ulonglong2*)&wp1[h];
                ulonglong2 w0v = *(const ulonglong2*)&wp0[h];
                FMA2(g2a, zv.x, w1v.x);
                FMA2(g2a, zv.y, w1v.y);
                FMA2(p2a, zv.x, w0v.x);
                FMA2(p2a, zv.y, w0v.y);
            }
            sx1[f * 128 + k] = hadd2(g2a);
            P0[o] = hadd2(p2a);
        }
    }
    __syncthreads();

    // ================= Phase 5: partials of HW@G (j-split 2) =================
    {
        float* P5 = U + 640;
        const int k = tid & 127, q = tid >> 7;
        const int jb = 64 * q;
        const float* hr = &HWs[k * HWS + jb];
        ull a2[5] = {0ull, 0ull, 0ull, 0ull, 0ull};
#pragma unroll 4
        for (int j = 0; j < 64; j += 4) {
            ulonglong2 h2v = *(const ulonglong2*)&hr[j];
#pragma unroll
            for (int f = 0; f < 5; f++) {
                ulonglong2 gv = *(const ulonglong2*)&sx1[f * 128 + jb + j];
                FMA2(a2[f], h2v.x, gv.x);
                FMA2(a2[f], h2v.y, gv.y);
            }
        }
#pragma unroll
        for (int f = 0; f < 5; f++)
            P5[q * 640 + f * 128 + k] = hadd2(a2[f]);
    }
    __syncthreads();

    // ===== x update + fused band-0 reduction =====
    {
        float bs = 0.f;
        for (int o = tid; o < 640; o += NTHREADS) {
            float v = xs[o] + U[o] + U[640 + o] + U[1280 + o];
            xs[o] = v;
            if (o < 128) bs = v;
        }
        if (tid < 128) {
#pragma unroll
            for (int m = 16; m > 0; m >>= 1) bs += __shfl_xor_sync(0xffffffffu, bs, m);
            if ((tid & 31) == 0) red[8 + (tid >> 5)] = bs;
        }
    }
    __syncthreads();

    // ===== projection + band clamps + output x (fused) =====
    {
        float fproj = red[8] + red[9] + red[10] + red[11] - 10.0f;
        float nu3 = gnu3[0], tg = gtg[0];
        float Vnu = 1.f - 1.f / ((1.f + nu3) * (1.f + nu3));
        float Vg  = 1.f - 1.f / ((1.f + tg) * (1.f + tg));
        float* outx = out + (size_t)b * 640;
        for (int m = tid; m < 640; m += NTHREADS) {
            float v = xs[m];
            int band = m >> 7;
            if (band == 0 && fproj > 0.f) v -= fproj * (1.f / 128.f);
            v = fmaxf(v, band == 1 ? nu3 : 0.f);
            if (band == 2) v = fminf(v, tg);
            if (band == 3) v = fminf(fmaxf(v, Vnu), Vg);
            xs[m] = v;
            outx[m] = v;
        }
    }
    __syncthreads();

    // ================= dacc partials + final outputs =================
    {
        float* dp = U + 1920;
        const int k = tid & 127, q = tid >> 7;
        float a = 0.f;
#pragma unroll 8
        for (int i = 64 * q; i < 64 * q + 64; i++)
            a += xs[i] * HWs[i * HWS + k];
        dp[q * 128 + k] = a;
    }
    __syncthreads();
    {
        const float* dp = U + 1920;
        const size_t BM = (size_t)Bsz * 640;
        const size_t BK = (size_t)Bsz * 128;
        if (tid < 128) {
            int k = tid;
            float p  = xs[k];
            float nu = xs[128 + k];
            float xg = xs[256 + k];
            float xv = xs[384 + k];
            float s4 = xs[512 + k];
            float f5 = 1.f - 1.f / ((1.f + xg) * (1.f + xg)) - xv;
            float f6 = sqrtf(xv) - s4;
            float dacc = dp[k] + dp[128 + k];
            float top  = p * HWs[k * HWS + k];
            float down = dacc - top + 1.f;
            out[BM +            (size_t)b * 128 + k] = f5;
            out[BM +     BK +   (size_t)b * 128 + k] = f6;
            out[BM + 2 * BK +   (size_t)b * 128 + k] = top - down * xg;
            out[BM + 3 * BK +   (size_t)b * 128 + k] = nu * down - top;
        }
    }
}

extern "C" void kernel_launch(void* const* d_in, const int* in_sizes, int n_in,
                              void* d_out, int out_size) {
    const float* HW    = (const float*)d_in[2];
    const float* x0    = (const float*)d_in[3];
    const float* nu3   = (const float*)d_in[4];
    const float* tg    = (const float*)d_in[5];
    const float* g1W0a = (const float*)d_in[12];
    const float* g1W1a = (const float*)d_in[13];
    const float* g1W0b = (const float*)d_in[14];
    const float* g1W1b = (const float*)d_in[15];
    const float* g2W0a = (const float*)d_in[16];
    const float* g2W1a = (const float*)d_in[17];
    const float* g2W0b = (const float*)d_in[18];
    const float* g2W1b = (const float*)d_in[19];

    cudaFuncSetAttribute(unfold_pocs_kernel,
                         cudaFuncAttributeMaxDynamicSharedMemorySize, SMEM_BYTES);

    unfold_pocs_kernel<<<Bsz, NTHREADS, SMEM_BYTES>>>(
        HW, x0, nu3, tg,
        g1W0a, g1W1a, g1W0b, g1W1b,
        g2W0a, g2W1a, g2W0b, g2W1b,
        (float*)d_out);
}

// round 14
// speedup vs baseline: 1.0883x; 1.0325x over previous
#include <cuda_runtime.h>
#include <math.h>
#include <stdint.h>

#define Bsz 2048
#define NTHREADS 256
#define HWS 132

typedef unsigned long long ull;

// ---- smem layout (float offsets) ----
#define O_HW   0        // 16896 : HW row-major stride 132
#define O_U    16896    // 9216 union region:
                        //  phase0/1: WBF (W64 frag) 8192 @ +0 ; X1t frag 1024 @ +8192
                        //  GNN1 : Wct frag 512 @ +5376 ; part 512 @ +5888 ; cpart 256 @ +6400
                        //  ph2/3/5: VBF frag 4096 @ +0 ; Gfh 1024 @ +4096 ; Gfl 1024 @ +5120 ;
                        //           P0 640 @ +6144 ; dacc 256 @ +6784
#define O_XS   26112    // 640
#define O_SX1  26752    // 640 (SX1, later HWG)
#define O_SW   27392    // 1088
#define O_RED  28608    // 64
#define SMEM_FLOATS 28672
#define SMEM_BYTES (SMEM_FLOATS * 4)   // 114688 B -> 2 CTAs/SM

__device__ __forceinline__ uint32_t tf32r(float x) {
    uint32_t u; asm("cvt.rna.tf32.f32 %0, %1;" : "=r"(u) : "f"(x)); return u;
}
__device__ __forceinline__ void mma_tf32(float* c, const uint32_t* a, uint32_t b0, uint32_t b1) {
    asm volatile(
        "mma.sync.aligned.m16n8k8.row.col.f32.tf32.tf32.f32 "
        "{%0,%1,%2,%3}, {%4,%5,%6,%7}, {%8,%9}, {%0,%1,%2,%3};"
        : "+f"(c[0]), "+f"(c[1]), "+f"(c[2]), "+f"(c[3])
        : "r"(a[0]), "r"(a[1]), "r"(a[2]), "r"(a[3]), "r"(b0), "r"(b1));
}

__global__ __launch_bounds__(NTHREADS, 2)
void unfold_pocs_kernel(const float* __restrict__ gHW, const float* __restrict__ gx0,
                        const float* __restrict__ gnu3, const float* __restrict__ gtg,
                        const float* __restrict__ g1W0a, const float* __restrict__ g1W1a,
                        const float* __restrict__ g1W0b, const float* __restrict__ g1W1b,
                        const float* __restrict__ g2W0a, const float* __restrict__ g2W1a,
                        const float* __restrict__ g2W0b, const float* __restrict__ g2W1b,
                        float* __restrict__ out) {
    extern __shared__ float sm[];
    const int b = blockIdx.x;
    const int tid = threadIdx.x;
    const int wid = tid >> 5;
    const int lid = tid & 31;
    const int lr = lid >> 2;   // 0..7
    const int lc = lid & 3;    // 0..3

    float* HWs = sm + O_HW;
    float* U   = sm + O_U;
    float* xs  = sm + O_XS;
    float* sx1 = sm + O_SX1;
    float* sw  = sm + O_SW;
    float* red = sm + O_RED;

    const float* hwg = gHW + (size_t)b * (128 * 128);

    // ================= Phase 0: loads =================
    for (int o = tid; o < 4096; o += NTHREADS) {
        float4 v = *(const float4*)(hwg + o * 4);
        int w = o * 4;
        int row = w >> 7, col = w & 127;
        *(float4*)&HWs[row * HWS + col] = v;
    }
    for (int o = tid; o < 160; o += NTHREADS)
        *(float4*)&xs[o * 4] = *(const float4*)(gx0 + (size_t)b * 640 + o * 4);
    // W64 fragment build: conflict-free float4 STS (chunk-lane identity)
    {
        float* WBF = U;
        for (int o = tid; o < 2048; o += NTHREADS) {
            int chunk = o >> 5, lane = o & 31;
            int kc = chunk >> 3, nt = chunk & 7;
            int k3 = lane & 3, hq = lane >> 2;
            const float* src = (nt < 4) ? (g2W0a + (nt * 8 + hq)) : (g2W1a + ((nt - 4) * 8 + hq));
            int kbase = kc * 16 + k3;
            float4 v;
            v.x = src[(kbase)      * 32];
            v.y = src[(kbase + 4)  * 32];
            v.z = src[(kbase + 8)  * 32];
            v.w = src[(kbase + 12) * 32];
            *(float4*)&WBF[(chunk << 7) + (lane << 2)] = v;
        }
    }
    // X1t frag build (N=8): conflict-free float4 STS
    {
        float* X1t = U + 8192;
        const float* gx = gx0 + (size_t)b * 640;
        for (int o = tid; o < 256; o += NTHREADS) {
            int chunk = o >> 5, lane = o & 31;     // chunk = kc
            int k3 = lane & 3, f = lane >> 2;
            int kbase = chunk * 16 + k3;
            float4 v = make_float4(0.f, 0.f, 0.f, 0.f);
            if (f < 5) {
                const float* src = gx + f * 128;
                v.x = src[kbase];
                v.y = src[kbase + 4];
                v.z = src[kbase + 8];
                v.w = src[kbase + 12];
            }
            *(float4*)&X1t[(chunk << 7) + (lane << 2)] = v;
        }
    }
    for (int o = tid; o < 160; o += NTHREADS) sw[o]       = g1W0a[o];
    for (int o = tid; o < 160; o += NTHREADS) sw[160 + o] = g1W1a[o];
    for (int o = tid; o < 64;  o += NTHREADS) sw[320 + o] = g1W0b[o];
    for (int o = tid; o < 64;  o += NTHREADS) sw[384 + o] = g1W1b[o];
    for (int o = tid; o < 160; o += NTHREADS) sw[448 + o] = g2W0a[128 * 32 + o];
    for (int o = tid; o < 160; o += NTHREADS) sw[608 + o] = g2W1a[128 * 32 + o];
    for (int o = tid; o < 160; o += NTHREADS) {
        int f = o >> 5, h = o & 31;
        sw[768 + f * 32 + h] = g2W0b[h * 5 + f];
        sw[928 + f * 32 + h] = g2W1b[h * 5 + f];
    }
    __syncthreads();

    float acc[8][4];     // T fragments, then U0 in acc[0..3]
    float acc2[4][4];    // phase1: acc2[0] = SX1 tile ; later HW@V fragments
    const int m0 = wid * 16;

    // ================= Phase 1: [T | SX1] = HW @ [W64 | X1] via HMMA tf32 =================
    {
        const float* WBF = U;
        const float* X1t = U + 8192;
#pragma unroll
        for (int nt = 0; nt < 8; nt++)
#pragma unroll
            for (int c = 0; c < 4; c++) acc[nt][c] = 0.f;
#pragma unroll
        for (int c = 0; c < 4; c++) acc2[0][c] = 0.f;
#pragma unroll
        for (int kc = 0; kc < 8; kc++) {
            const int k0 = kc * 16;
            uint32_t a0[4], a1[4];
            a0[0] = __float_as_uint(HWs[(m0 + lr)     * HWS + k0 + lc]);
            a0[1] = __float_as_uint(HWs[(m0 + lr + 8) * HWS + k0 + lc]);
            a0[2] = __float_as_uint(HWs[(m0 + lr)     * HWS + k0 + lc + 4]);
            a0[3] = __float_as_uint(HWs[(m0 + lr + 8) * HWS + k0 + lc + 4]);
            a1[0] = __float_as_uint(HWs[(m0 + lr)     * HWS + k0 + 8 + lc]);
            a1[1] = __float_as_uint(HWs[(m0 + lr + 8) * HWS + k0 + 8 + lc]);
            a1[2] = __float_as_uint(HWs[(m0 + lr)     * HWS + k0 + 12 + lc]);
            a1[3] = __float_as_uint(HWs[(m0 + lr + 8) * HWS + k0 + 12 + lc]);
#pragma unroll
            for (int nt = 0; nt < 8; nt++) {
                float4 bv = *(const float4*)&WBF[((kc << 3) + nt) << 7 | (lid << 2)];
                mma_tf32(acc[nt], a0, __float_as_uint(bv.x), __float_as_uint(bv.y));
                mma_tf32(acc[nt], a1, __float_as_uint(bv.z), __float_as_uint(bv.w));
            }
            {
                float4 bv = *(const float4*)&X1t[(kc << 7) | (lid << 2)];
                mma_tf32(acc2[0], a0, __float_as_uint(bv.x), __float_as_uint(bv.y));
                mma_tf32(acc2[0], a1, __float_as_uint(bv.z), __float_as_uint(bv.w));
            }
        }
        int f0 = 2 * lc, f1 = 2 * lc + 1;
        if (f0 < 5) {
            sx1[f0 * 128 + m0 + lr]     = acc2[0][0];
            sx1[f0 * 128 + m0 + lr + 8] = acc2[0][2];
        }
        if (f1 < 5) {
            sx1[f1 * 128 + m0 + lr]     = acc2[0][1];
            sx1[f1 * 128 + m0 + lr + 8] = acc2[0][3];
        }
    }
    __syncthreads();   // WBF/X1t dead; sx1 = SX1 ready

    // ================= GNN1 (HMMA, Z1 reduced in registers) =================
    {
        float* Wct   = U + 5376;   // cat-weights frag (k=16, N=32)
        float* part  = U + 5888;   // 512: warp partials (sums | wsums)
        float* cpart = U + 6400;   // 256: colmean partials

        for (int o = tid; o < 128; o += NTHREADS) {
            int chunk = o >> 5, lane = o & 31;   // chunk = h>>3 (0..3)
            int k3 = lane & 3, hq = lane >> 2;
            int h = chunk * 8 + hq;
            float4 v;
#pragma unroll
            for (int c = 0; c < 4; c++) {
                int k = k3 + 4 * c;
                float x = (k < 5) ? sw[k * 32 + h] : (k < 10 ? sw[160 + (k - 5) * 32 + h] : 0.f);
                ((float*)&v)[c] = x;
            }
            *(float4*)&Wct[(chunk << 7) + (lane << 2)] = v;
        }
        {
            int col = tid & 127, half = tid >> 7;
            float a = 0.f;
#pragma unroll 4
            for (int i = 64 * half; i < 64 * half + 64; i++)
                a += HWs[i * HWS + col];
            cpart[half * 128 + col] = a;
        }
        __syncthreads();

        // Z1 = relu(cat @ Wct) via HMMA; reduce rows in registers
        {
            const int row0 = m0 + lr, row1 = row0 + 8;
            float cr0 = (cpart[row0] + cpart[128 + row0]) * (1.f / 128.f);
            float cr1 = (cpart[row1] + cpart[128 + row1]) * (1.f / 128.f);
            uint32_t a0[4], a1[4];
            a0[0] = __float_as_uint(xs[lc * 128 + row0]);
            a0[1] = __float_as_uint(xs[lc * 128 + row1]);
            a0[2] = __float_as_uint((lc == 0) ? xs[4 * 128 + row0] : sx1[(lc - 1) * 128 + row0]);
            a0[3] = __float_as_uint((lc == 0) ? xs[4 * 128 + row1] : sx1[(lc - 1) * 128 + row1]);
            a1[0] = (lc < 2) ? __float_as_uint(sx1[(lc + 3) * 128 + row0]) : 0u;
            a1[1] = (lc < 2) ? __float_as_uint(sx1[(lc + 3) * 128 + row1]) : 0u;
            a1[2] = 0u;
            a1[3] = 0u;
#pragma unroll
            for (int nt = 0; nt < 4; nt++) {
                float cz[4] = {0.f, 0.f, 0.f, 0.f};
                float4 bv = *(const float4*)&Wct[(nt << 7) | (lid << 2)];
                mma_tf32(cz, a0, __float_as_uint(bv.x), __float_as_uint(bv.y));
                mma_tf32(cz, a1, __float_as_uint(bv.z), __float_as_uint(bv.w));
                float r0 = fmaxf(cz[0], 0.f), r1 = fmaxf(cz[1], 0.f);
                float r2 = fmaxf(cz[2], 0.f), r3 = fmaxf(cz[3], 0.f);
                float s0 = r0 + r2, s1 = r1 + r3;
                float w0 = cr0 * r0 + cr1 * r2, w1 = cr0 * r1 + cr1 * r3;
#pragma unroll
                for (int msk = 4; msk <= 16; msk <<= 1) {
                    s0 += __shfl_xor_sync(0xffffffffu, s0, msk);
                    s1 += __shfl_xor_sync(0xffffffffu, s1, msk);
                    w0 += __shfl_xor_sync(0xffffffffu, w0, msk);
                    w1 += __shfl_xor_sync(0xffffffffu, w1, msk);
                }
                if (lr == 0) {
                    part[wid * 32 + nt * 8 + 2 * lc]           = s0;
                    part[wid * 32 + nt * 8 + 2 * lc + 1]       = s1;
                    part[256 + wid * 32 + nt * 8 + 2 * lc]     = w0;
                    part[256 + wid * 32 + nt * 8 + 2 * lc + 1] = w1;
                }
            }
        }
        __syncthreads();
        if (tid < 32) {
            float m = 0.f, cz = 0.f;
#pragma unroll
            for (int q = 0; q < 8; q++) {
                m  += part[q * 32 + tid];
                cz += part[256 + q * 32 + tid];
            }
            red[tid] = m * (1.f / 128.f);
            red[32 + tid] = cz;
        }
        __syncthreads();
        if (tid < 2) {
            const float* w0b = sw + 320;
            const float* w1b = sw + 384;
            float a = 0.f;
#pragma unroll 8
            for (int h = 0; h < 32; h++)
                a += red[h] * w0b[h * 2 + tid] + red[32 + h] * w1b[h * 2 + tid];
            red[62 + tid] = fmaxf(a, 0.f);   // lbd
        }
        __syncthreads();
        if (tid < 128) {
            float l0 = red[62], l1 = red[63];
            float s1v = xs[128 + tid];
            xs[128 + tid] = s1v - l0 * ((1.0f / 128.f) / (1.f + s1v));
            xs[512 + tid] += l1 * ((1.0f / 128.f) * 0.1f);
        }
    }
    __syncthreads();   // xs final

    // ====== Phase 2+3 (+fused G/P0): U0 in regs, V frag, HMMA HW@V, reg-z2 ======
    {
        float* VBF = U;            // V fragment order (N=32 -> 4 n-tiles)
        float* Gfh = U + 4096;
        float* Gfl = U + 5120;
        float* P0  = U + 6144;
        const float* w0bot = sw + 448;
        const float* w1bot = sw + 608;

        // zero G fragment pads (f=5..7 and all, overwritten below for f<5)
        for (int o = tid; o < 512; o += NTHREADS)
            *(float4*)&U[4096 + o * 4] = make_float4(0.f, 0.f, 0.f, 0.f);

        float xr[2][5];
#pragma unroll
        for (int f = 0; f < 5; f++) {
            xr[0][f] = xs[f * 128 + m0 + lr];
            xr[1][f] = xs[f * 128 + m0 + lr + 8];
        }
        const int lr3 = lr & 3, lrh = lr >> 2;
#pragma unroll
        for (int nt = 0; nt < 8; nt++) {
            const bool isU = nt < 4;
            const float* wb = isU ? w0bot : w1bot;
            const int hb = (isU ? nt : nt - 4) * 8 + 2 * lc;
            float r00 = acc[nt][0], r01 = acc[nt][1];
            float r10 = acc[nt][2], r11 = acc[nt][3];
#pragma unroll
            for (int f = 0; f < 5; f++) {
                float w0 = wb[f * 32 + hb], w1 = wb[f * 32 + hb + 1];
                r00 += xr[0][f] * w0; r01 += xr[0][f] * w1;
                r10 += xr[1][f] * w0; r11 += xr[1][f] * w1;
            }
            if (isU) {
                acc[nt][0] = r00; acc[nt][1] = r01; acc[nt][2] = r10; acc[nt][3] = r11;
            } else {
                const int ch = ((wid * 4) + (nt - 4)) << 7;
                const int p0 = ch | (((2 * lc) * 4 + lr3) << 2);
                const int p1 = ch | (((2 * lc + 1) * 4 + lr3) << 2);
                VBF[p0 + lrh]     = r00;
                VBF[p1 + lrh]     = r01;
                VBF[p0 + 2 + lrh] = r10;
                VBF[p1 + 2 + lrh] = r11;
            }
        }
        __syncthreads();   // V fully written; G pads zeroed

#pragma unroll
        for (int nt = 0; nt < 4; nt++)
#pragma unroll
            for (int c = 0; c < 4; c++) acc2[nt][c] = 0.f;
#pragma unroll
        for (int kc = 0; kc < 8; kc++) {
            const int k0 = kc * 16;
            uint32_t a0[4], a1[4];
            a0[0] = __float_as_uint(HWs[(m0 + lr)     * HWS + k0 + lc]);
            a0[1] = __float_as_uint(HWs[(m0 + lr + 8) * HWS + k0 + lc]);
            a0[2] = __float_as_uint(HWs[(m0 + lr)     * HWS + k0 + lc + 4]);
            a0[3] = __float_as_uint(HWs[(m0 + lr + 8) * HWS + k0 + lc + 4]);
            a1[0] = __float_as_uint(HWs[(m0 + lr)     * HWS + k0 + 8 + lc]);
            a1[1] = __float_as_uint(HWs[(m0 + lr + 8) * HWS + k0 + 8 + lc]);
            a1[2] = __float_as_uint(HWs[(m0 + lr)     * HWS + k0 + 12 + lc]);
            a1[3] = __float_as_uint(HWs[(m0 + lr + 8) * HWS + k0 + 12 + lc]);
#pragma unroll
            for (int nt = 0; nt < 4; nt++) {
                float4 bv = *(const float4*)&VBF[((kc << 2) + nt) << 7 | (lid << 2)];
                mma_tf32(acc2[nt], a0, __float_as_uint(bv.x), __float_as_uint(bv.y));
                mma_tf32(acc2[nt], a1, __float_as_uint(bv.z), __float_as_uint(bv.w));
            }
        }

        // ---- fused G = Z2@W1b, P0 = Z2@W0b with z2 in registers ----
        float g0[5], g1[5], p0r[5], p1r[5];
#pragma unroll
        for (int f = 0; f < 5; f++) { g0[f] = 0.f; g1[f] = 0.f; p0r[f] = 0.f; p1r[f] = 0.f; }
#pragma unroll
        for (int nt = 0; nt < 4; nt++) {
            const int h0 = nt * 8 + 2 * lc;
            float z00 = fmaxf(acc[nt][0] + acc2[nt][0], 0.f);
            float z01 = fmaxf(acc[nt][1] + acc2[nt][1], 0.f);
            float z10 = fmaxf(acc[nt][2] + acc2[nt][2], 0.f);
            float z11 = fmaxf(acc[nt][3] + acc2[nt][3], 0.f);
#pragma unroll
            for (int f = 0; f < 5; f++) {
                float wa0 = sw[768 + f * 32 + h0], wa1 = sw[768 + f * 32 + h0 + 1];
                float wb0 = sw[928 + f * 32 + h0], wb1 = sw[928 + f * 32 + h0 + 1];
                g0[f]  += z00 * wb0 + z01 * wb1;
                g1[f]  += z10 * wb0 + z11 * wb1;
                p0r[f] += z00 * wa0 + z01 * wa1;
                p1r[f] += z10 * wa0 + z11 * wa1;
            }
        }
#pragma unroll
        for (int f = 0; f < 5; f++) {
            g0[f]  += __shfl_xor_sync(0xffffffffu, g0[f], 1);
            g0[f]  += __shfl_xor_sync(0xffffffffu, g0[f], 2);
            g1[f]  += __shfl_xor_sync(0xffffffffu, g1[f], 1);
            g1[f]  += __shfl_xor_sync(0xffffffffu, g1[f], 2);
            p0r[f] += __shfl_xor_sync(0xffffffffu, p0r[f], 1);
            p0r[f] += __shfl_xor_sync(0xffffffffu, p0r[f], 2);
            p1r[f] += __shfl_xor_sync(0xffffffffu, p1r[f], 1);
            p1r[f] += __shfl_xor_sync(0xffffffffu, p1r[f], 2);
        }
        if (lc == 0) {
            const int r0 = m0 + lr, r1 = r0 + 8;
#pragma unroll
            for (int f = 0; f < 5; f++) {
                int pos0 = ((r0 >> 4) << 7) | ((f * 4 + (r0 & 3)) << 2) | ((r0 >> 2) & 3);
                int pos1 = ((r1 >> 4) << 7) | ((f * 4 + (r1 & 3)) << 2) | ((r1 >> 2) & 3);
                float gA = g0[f];
                float ghA = __uint_as_float(tf32r(gA));
                Gfh[pos0] = ghA; Gfl[pos0] = gA - ghA;
                float gB = g1[f];
                float ghB = __uint_as_float(tf32r(gB));
                Gfh[pos1] = ghB; Gfl[pos1] = gB - ghB;
                P0[f * 128 + r0] = p0r[f];
                P0[f * 128 + r1] = p1r[f];
            }
        }
    }
    __syncthreads();

    // ================= Phase 5: HWG = HW@G via HMMA (2-term B split) =================
    {
        const float* Gfh = U + 4096;
        const float* Gfl = U + 5120;
        float c[4] = {0.f, 0.f, 0.f, 0.f};
#pragma unroll
        for (int kc = 0; kc < 8; kc++) {
            const int k0 = kc * 16;
            uint32_t a0[4], a1[4];
            a0[0] = __float_as_uint(HWs[(m0 + lr)     * HWS + k0 + lc]);
            a0[1] = __float_as_uint(HWs[(m0 + lr + 8) * HWS + k0 + lc]);
            a0[2] = __float_as_uint(HWs[(m0 + lr)     * HWS + k0 + lc + 4]);
            a0[3] = __float_as_uint(HWs[(m0 + lr + 8) * HWS + k0 + lc + 4]);
            a1[0] = __float_as_uint(HWs[(m0 + lr)     * HWS + k0 + 8 + lc]);
            a1[1] = __float_as_uint(HWs[(m0 + lr + 8) * HWS + k0 + 8 + lc]);
            a1[2] = __float_as_uint(HWs[(m0 + lr)     * HWS + k0 + 12 + lc]);
            a1[3] = __float_as_uint(HWs[(m0 + lr + 8) * HWS + k0 + 12 + lc]);
            float4 bh = *(const float4*)&Gfh[(kc << 7) | (lid << 2)];
            float4 bl = *(const float4*)&Gfl[(kc << 7) | (lid << 2)];
            mma_tf32(c, a0, __float_as_uint(bh.x), __float_as_uint(bh.y));
            mma_tf32(c, a1, __float_as_uint(bh.z), __float_as_uint(bh.w));
            mma_tf32(c, a0, __float_as_uint(bl.x), __float_as_uint(bl.y));
            mma_tf32(c, a1, __float_as_uint(bl.z), __float_as_uint(bl.w));
        }
        int f0 = 2 * lc, f1 = 2 * lc + 1;
        if (f0 < 5) {
            sx1[f0 * 128 + m0 + lr]     = c[0];
            sx1[f0 * 128 + m0 + lr + 8] = c[2];
        }
        if (f1 < 5) {
            sx1[f1 * 128 + m0 + lr]     = c[1];
            sx1[f1 * 128 + m0 + lr + 8] = c[3];
        }
    }
    __syncthreads();

    // ===== x update + fused band-0 reduction =====
    {
        float bs = 0.f;
        for (int o = tid; o < 640; o += NTHREADS) {
            float v = xs[o] + U[6144 + o] + sx1[o];
            xs[o] = v;
            if (o < 128) bs = v;
        }
        if (tid < 128) {
#pragma unroll
            for (int m = 16; m > 0; m >>= 1) bs += __shfl_xor_sync(0xffffffffu, bs, m);
            if ((tid & 31) == 0) red[8 + (tid >> 5)] = bs;
        }
    }
    __syncthreads();

    // ===== projection + band clamps + output x (fused) =====
    {
        float fproj = red[8] + red[9] + red[10] + red[11] - 10.0f;
        float nu3 = gnu3[0], tg = gtg[0];
        float Vnu = 1.f - 1.f / ((1.f + nu3) * (1.f + nu3));
        float Vg  = 1.f - 1.f / ((1.f + tg) * (1.f + tg));
        float* outx = out + (size_t)b * 640;
        for (int m = tid; m < 640; m += NTHREADS) {
            float v = xs[m];
            int band = m >> 7;
            if (band == 0 && fproj > 0.f) v -= fproj * (1.f / 128.f);
            v = fmaxf(v, band == 1 ? nu3 : 0.f);
            if (band == 2) v = fminf(v, tg);
            if (band == 3) v = fminf(fmaxf(v, Vnu), Vg);
            xs[m] = v;
            outx[m] = v;
        }
    }
    __syncthreads();

    // ================= dacc partials + final outputs =================
    {
        float* dp = U + 6784;
        const int k = tid & 127, q = tid >> 7;
        float a = 0.f;
#pragma unroll 8
        for (int i = 64 * q; i < 64 * q + 64; i++)
            a += xs[i] * HWs[i * HWS + k];
        dp[q * 128 + k] = a;
    }
    __syncthreads();
    {
        const float* dp = U + 6784;
        const size_t BM = (size_t)Bsz * 640;
        const size_t BK = (size_t)Bsz * 128;
        if (tid < 128) {
            int k = tid;
            float p  = xs[k];
            float nu = xs[128 + k];
            float xg = xs[256 + k];
            float xv = xs[384 + k];
            float s4 = xs[512 + k];
            float f5 = 1.f - 1.f / ((1.f + xg) * (1.f + xg)) - xv;
            float f6 = sqrtf(xv) - s4;
            float dacc = dp[k] + dp[128 + k];
            float top  = p * HWs[k * HWS + k];
            float down = dacc - top + 1.f;
            out[BM +            (size_t)b * 128 + k] = f5;
            out[BM +     BK +   (size_t)b * 128 + k] = f6;
            out[BM + 2 * BK +   (size_t)b * 128 + k] = top - down * xg;
            out[BM + 3 * BK +   (size_t)b * 128 + k] = nu * down - top;
        }
    }
}

extern "C" void kernel_launch(void* const* d_in, const int* in_sizes, int n_in,
                              void* d_out, int out_size) {
    const float* HW    = (const float*)d_in[2];
    const float* x0    = (const float*)d_in[3];
    const float* nu3   = (const float*)d_in[4];
    const float* tg    = (const float*)d_in[5];
    const float* g1W0a = (const float*)d_in[12];
    const float* g1W1a = (const float*)d_in[13];
    const float* g1W0b = (const float*)d_in[14];
    const float* g1W1b = (const float*)d_in[15];
    const float* g2W0a = (const float*)d_in[16];
    const float* g2W1a = (const float*)d_in[17];
    const float* g2W0b = (const float*)d_in[18];
    const float* g2W1b = (const float*)d_in[19];

    cudaFuncSetAttribute(unfold_pocs_kernel,
                         cudaFuncAttributeMaxDynamicSharedMemorySize, SMEM_BYTES);

    unfold_pocs_kernel<<<Bsz, NTHREADS, SMEM_BYTES>>>(
        HW, x0, nu3, tg,
        g1W0a, g1W1a, g1W0b, g1W1b,
        g2W0a, g2W1a, g2W0b, g2W1b,
        (float*)d_out);
}

// round 15
// speedup vs baseline: 1.1086x; 1.0187x over previous
#include <cuda_runtime.h>
#include <math.h>
#include <stdint.h>

#define Bsz 2048
#define NTHREADS 256
#define HWS 132

typedef unsigned long long ull;

// ---- smem layout (float offsets) ----
#define O_HW   0        // 16896 : HW row-major stride 132
#define O_U    16896    // 9216 union region:
                        //  phase0/1: WBF (W64 frag) 8192 @ +0 ; X1t frag 1024 @ +8192
                        //  GNN1 : Wct frag 512 @ +5376 ; part 512 @ +5888 ; cpart 256 @ +6400
                        //  ph2/3/5: VBF frag 4096 @ +0 ; Gfh 1024 @ +4096 ; Gfl 1024 @ +5120 ;
                        //           P0 640 @ +6144 ; dacc 256 @ +6784
#define O_XS   26112    // 640
#define O_SX1  26752    // 640 (SX1 only)
#define O_SW   27392    // 1088
#define O_RED  28608    // 64
#define SMEM_FLOATS 28672
#define SMEM_BYTES (SMEM_FLOATS * 4)   // 114688 B -> 2 CTAs/SM

__device__ __forceinline__ uint32_t tf32r(float x) {
    uint32_t u; asm("cvt.rna.tf32.f32 %0, %1;" : "=r"(u) : "f"(x)); return u;
}
__device__ __forceinline__ void mma_tf32(float* c, const uint32_t* a, uint32_t b0, uint32_t b1) {
    asm volatile(
        "mma.sync.aligned.m16n8k8.row.col.f32.tf32.tf32.f32 "
        "{%0,%1,%2,%3}, {%4,%5,%6,%7}, {%8,%9}, {%0,%1,%2,%3};"
        : "+f"(c[0]), "+f"(c[1]), "+f"(c[2]), "+f"(c[3])
        : "r"(a[0]), "r"(a[1]), "r"(a[2]), "r"(a[3]), "r"(b0), "r"(b1));
}

__global__ __launch_bounds__(NTHREADS, 2)
void unfold_pocs_kernel(const float* __restrict__ gHW, const float* __restrict__ gx0,
                        const float* __restrict__ gnu3, const float* __restrict__ gtg,
                        const float* __restrict__ g1W0a, const float* __restrict__ g1W1a,
                        const float* __restrict__ g1W0b, const float* __restrict__ g1W1b,
                        const float* __restrict__ g2W0a, const float* __restrict__ g2W1a,
                        const float* __restrict__ g2W0b, const float* __restrict__ g2W1b,
                        float* __restrict__ out) {
    extern __shared__ float sm[];
    const int b = blockIdx.x;
    const int tid = threadIdx.x;
    const int wid = tid >> 5;
    const int lid = tid & 31;
    const int lr = lid >> 2;   // 0..7
    const int lc = lid & 3;    // 0..3

    float* HWs = sm + O_HW;
    float* U   = sm + O_U;
    float* xs  = sm + O_XS;
    float* sx1 = sm + O_SX1;
    float* sw  = sm + O_SW;
    float* red = sm + O_RED;

    const float* hwg = gHW + (size_t)b * (128 * 128);

    // ================= Phase 0: loads =================
    for (int o = tid; o < 4096; o += NTHREADS) {
        float4 v = *(const float4*)(hwg + o * 4);
        int w = o * 4;
        int row = w >> 7, col = w & 127;
        *(float4*)&HWs[row * HWS + col] = v;
    }
    for (int o = tid; o < 160; o += NTHREADS)
        *(float4*)&xs[o * 4] = *(const float4*)(gx0 + (size_t)b * 640 + o * 4);
    // W64 fragment build: conflict-free float4 STS (chunk-lane identity)
    {
        float* WBF = U;
        for (int o = tid; o < 2048; o += NTHREADS) {
            int chunk = o >> 5, lane = o & 31;
            int kc = chunk >> 3, nt = chunk & 7;
            int k3 = lane & 3, hq = lane >> 2;
            const float* src = (nt < 4) ? (g2W0a + (nt * 8 + hq)) : (g2W1a + ((nt - 4) * 8 + hq));
            int kbase = kc * 16 + k3;
            float4 v;
            v.x = src[(kbase)      * 32];
            v.y = src[(kbase + 4)  * 32];
            v.z = src[(kbase + 8)  * 32];
            v.w = src[(kbase + 12) * 32];
            *(float4*)&WBF[(chunk << 7) + (lane << 2)] = v;
        }
    }
    // X1t frag build (N=8): conflict-free float4 STS
    {
        float* X1t = U + 8192;
        const float* gx = gx0 + (size_t)b * 640;
        for (int o = tid; o < 256; o += NTHREADS) {
            int chunk = o >> 5, lane = o & 31;     // chunk = kc
            int k3 = lane & 3, f = lane >> 2;
            int kbase = chunk * 16 + k3;
            float4 v = make_float4(0.f, 0.f, 0.f, 0.f);
            if (f < 5) {
                const float* src = gx + f * 128;
                v.x = src[kbase];
                v.y = src[kbase + 4];
                v.z = src[kbase + 8];
                v.w = src[kbase + 12];
            }
            *(float4*)&X1t[(chunk << 7) + (lane << 2)] = v;
        }
    }
    for (int o = tid; o < 160; o += NTHREADS) sw[o]       = g1W0a[o];
    for (int o = tid; o < 160; o += NTHREADS) sw[160 + o] = g1W1a[o];
    for (int o = tid; o < 64;  o += NTHREADS) sw[320 + o] = g1W0b[o];
    for (int o = tid; o < 64;  o += NTHREADS) sw[384 + o] = g1W1b[o];
    for (int o = tid; o < 160; o += NTHREADS) sw[448 + o] = g2W0a[128 * 32 + o];
    for (int o = tid; o < 160; o += NTHREADS) sw[608 + o] = g2W1a[128 * 32 + o];
    for (int o = tid; o < 160; o += NTHREADS) {
        int f = o >> 5, h = o & 31;
        sw[768 + f * 32 + h] = g2W0b[h * 5 + f];
        sw[928 + f * 32 + h] = g2W1b[h * 5 + f];
    }
    __syncthreads();

    float acc[8][4];     // T fragments, then U0 in acc[0..3]
    float acc2[4][4];    // phase1: acc2[0] = SX1 tile ; later HW@V fragments
    const int m0 = wid * 16;

    // ================= Phase 1: [T | SX1] = HW @ [W64 | X1] via HMMA tf32 =================
    {
        const float* WBF = U;
        const float* X1t = U + 8192;
#pragma unroll
        for (int nt = 0; nt < 8; nt++)
#pragma unroll
            for (int c = 0; c < 4; c++) acc[nt][c] = 0.f;
#pragma unroll
        for (int c = 0; c < 4; c++) acc2[0][c] = 0.f;
#pragma unroll
        for (int kc = 0; kc < 8; kc++) {
            const int k0 = kc * 16;
            uint32_t a0[4], a1[4];
            a0[0] = __float_as_uint(HWs[(m0 + lr)     * HWS + k0 + lc]);
            a0[1] = __float_as_uint(HWs[(m0 + lr + 8) * HWS + k0 + lc]);
            a0[2] = __float_as_uint(HWs[(m0 + lr)     * HWS + k0 + lc + 4]);
            a0[3] = __float_as_uint(HWs[(m0 + lr + 8) * HWS + k0 + lc + 4]);
            a1[0] = __float_as_uint(HWs[(m0 + lr)     * HWS + k0 + 8 + lc]);
            a1[1] = __float_as_uint(HWs[(m0 + lr + 8) * HWS + k0 + 8 + lc]);
            a1[2] = __float_as_uint(HWs[(m0 + lr)     * HWS + k0 + 12 + lc]);
            a1[3] = __float_as_uint(HWs[(m0 + lr + 8) * HWS + k0 + 12 + lc]);
#pragma unroll
            for (int nt = 0; nt < 8; nt++) {
                float4 bv = *(const float4*)&WBF[((kc << 3) + nt) << 7 | (lid << 2)];
                mma_tf32(acc[nt], a0, __float_as_uint(bv.x), __float_as_uint(bv.y));
                mma_tf32(acc[nt], a1, __float_as_uint(bv.z), __float_as_uint(bv.w));
            }
            {
                float4 bv = *(const float4*)&X1t[(kc << 7) | (lid << 2)];
                mma_tf32(acc2[0], a0, __float_as_uint(bv.x), __float_as_uint(bv.y));
                mma_tf32(acc2[0], a1, __float_as_uint(bv.z), __float_as_uint(bv.w));
            }
        }
        int f0 = 2 * lc, f1 = 2 * lc + 1;
        if (f0 < 5) {
            sx1[f0 * 128 + m0 + lr]     = acc2[0][0];
            sx1[f0 * 128 + m0 + lr + 8] = acc2[0][2];
        }
        if (f1 < 5) {
            sx1[f1 * 128 + m0 + lr]     = acc2[0][1];
            sx1[f1 * 128 + m0 + lr + 8] = acc2[0][3];
        }
    }
    __syncthreads();   // WBF/X1t dead; sx1 = SX1 ready

    // ================= GNN1 (HMMA, Z1 reduced in registers) =================
    {
        float* Wct   = U + 5376;   // cat-weights frag (k=16, N=32)
        float* part  = U + 5888;   // 512: warp partials (sums | wsums)
        float* cpart = U + 6400;   // 256: colmean partials

        for (int o = tid; o < 128; o += NTHREADS) {
            int chunk = o >> 5, lane = o & 31;   // chunk = h>>3 (0..3)
            int k3 = lane & 3, hq = lane >> 2;
            int h = chunk * 8 + hq;
            float4 v;
#pragma unroll
            for (int c = 0; c < 4; c++) {
                int k = k3 + 4 * c;
                float x = (k < 5) ? sw[k * 32 + h] : (k < 10 ? sw[160 + (k - 5) * 32 + h] : 0.f);
                ((float*)&v)[c] = x;
            }
            *(float4*)&Wct[(chunk << 7) + (lane << 2)] = v;
        }
        {
            int col = tid & 127, half = tid >> 7;
            float a = 0.f;
#pragma unroll 4
            for (int i = 64 * half; i < 64 * half + 64; i++)
                a += HWs[i * HWS + col];
            cpart[half * 128 + col] = a;
        }
        __syncthreads();

        // Z1 = relu(cat @ Wct) via HMMA; reduce rows in registers
        {
            const int row0 = m0 + lr, row1 = row0 + 8;
            float cr0 = (cpart[row0] + cpart[128 + row0]) * (1.f / 128.f);
            float cr1 = (cpart[row1] + cpart[128 + row1]) * (1.f / 128.f);
            uint32_t a0[4], a1[4];
            a0[0] = __float_as_uint(xs[lc * 128 + row0]);
            a0[1] = __float_as_uint(xs[lc * 128 + row1]);
            a0[2] = __float_as_uint((lc == 0) ? xs[4 * 128 + row0] : sx1[(lc - 1) * 128 + row0]);
            a0[3] = __float_as_uint((lc == 0) ? xs[4 * 128 + row1] : sx1[(lc - 1) * 128 + row1]);
            a1[0] = (lc < 2) ? __float_as_uint(sx1[(lc + 3) * 128 + row0]) : 0u;
            a1[1] = (lc < 2) ? __float_as_uint(sx1[(lc + 3) * 128 + row1]) : 0u;
            a1[2] = 0u;
            a1[3] = 0u;
#pragma unroll
            for (int nt = 0; nt < 4; nt++) {
                float cz[4] = {0.f, 0.f, 0.f, 0.f};
                float4 bv = *(const float4*)&Wct[(nt << 7) | (lid << 2)];
                mma_tf32(cz, a0, __float_as_uint(bv.x), __float_as_uint(bv.y));
                mma_tf32(cz, a1, __float_as_uint(bv.z), __float_as_uint(bv.w));
                float r0 = fmaxf(cz[0], 0.f), r1 = fmaxf(cz[1], 0.f);
                float r2 = fmaxf(cz[2], 0.f), r3 = fmaxf(cz[3], 0.f);
                float s0 = r0 + r2, s1 = r1 + r3;
                float w0 = cr0 * r0 + cr1 * r2, w1 = cr0 * r1 + cr1 * r3;
#pragma unroll
                for (int msk = 4; msk <= 16; msk <<= 1) {
                    s0 += __shfl_xor_sync(0xffffffffu, s0, msk);
                    s1 += __shfl_xor_sync(0xffffffffu, s1, msk);
                    w0 += __shfl_xor_sync(0xffffffffu, w0, msk);
                    w1 += __shfl_xor_sync(0xffffffffu, w1, msk);
                }
                if (lr == 0) {
                    part[wid * 32 + nt * 8 + 2 * lc]           = s0;
                    part[wid * 32 + nt * 8 + 2 * lc + 1]       = s1;
                    part[256 + wid * 32 + nt * 8 + 2 * lc]     = w0;
                    part[256 + wid * 32 + nt * 8 + 2 * lc + 1] = w1;
                }
            }
        }
        __syncthreads();
        // fused combine + lbd (warp 0)
        if (tid < 32) {
            float m = 0.f, cz = 0.f;
#pragma unroll
            for (int q = 0; q < 8; q++) {
                m  += part[q * 32 + tid];
                cz += part[256 + q * 32 + tid];
            }
            m *= (1.f / 128.f);
            float l0 = m * sw[320 + tid * 2]     + cz * sw[384 + tid * 2];
            float l1 = m * sw[320 + tid * 2 + 1] + cz * sw[384 + tid * 2 + 1];
#pragma unroll
            for (int msk = 16; msk > 0; msk >>= 1) {
                l0 += __shfl_xor_sync(0xffffffffu, l0, msk);
                l1 += __shfl_xor_sync(0xffffffffu, l1, msk);
            }
            if (tid == 0) {
                red[62] = fmaxf(l0, 0.f);
                red[63] = fmaxf(l1, 0.f);
            }
        }
        __syncthreads();
        if (tid < 128) {
            float l0 = red[62], l1 = red[63];
            float s1v = xs[128 + tid];
            xs[128 + tid] = s1v - l0 * ((1.0f / 128.f) / (1.f + s1v));
            xs[512 + tid] += l1 * ((1.0f / 128.f) * 0.1f);
        }
    }
    __syncthreads();   // xs final

    // ====== Phase 2+3 (+fused G/P0): U0 in regs, V frag, HMMA HW@V, reg-z2 ======
    {
        float* VBF = U;            // V fragment order (N=32 -> 4 n-tiles)
        float* Gfh = U + 4096;
        float* Gfl = U + 5120;
        float* P0  = U + 6144;
        const float* w0bot = sw + 448;
        const float* w1bot = sw + 608;

        // zero G fragment pads (overwritten below for f<5)
        for (int o = tid; o < 512; o += NTHREADS)
            *(float4*)&U[4096 + o * 4] = make_float4(0.f, 0.f, 0.f, 0.f);

        float xr[2][5];
#pragma unroll
        for (int f = 0; f < 5; f++) {
            xr[0][f] = xs[f * 128 + m0 + lr];
            xr[1][f] = xs[f * 128 + m0 + lr + 8];
        }
        const int lr3 = lr & 3, lrh = lr >> 2;
#pragma unroll
        for (int nt = 0; nt < 8; nt++) {
            const bool isU = nt < 4;
            const float* wb = isU ? w0bot : w1bot;
            const int hb = (isU ? nt : nt - 4) * 8 + 2 * lc;
            float r00 = acc[nt][0], r01 = acc[nt][1];
            float r10 = acc[nt][2], r11 = acc[nt][3];
#pragma unroll
            for (int f = 0; f < 5; f++) {
                float w0 = wb[f * 32 + hb], w1 = wb[f * 32 + hb + 1];
                r00 += xr[0][f] * w0; r01 += xr[0][f] * w1;
                r10 += xr[1][f] * w0; r11 += xr[1][f] * w1;
            }
            if (isU) {
                acc[nt][0] = r00; acc[nt][1] = r01; acc[nt][2] = r10; acc[nt][3] = r11;
            } else {
                const int ch = ((wid * 4) + (nt - 4)) << 7;
                const int p0 = ch | (((2 * lc) * 4 + lr3) << 2);
                const int p1 = ch | (((2 * lc + 1) * 4 + lr3) << 2);
                VBF[p0 + lrh]     = r00;
                VBF[p1 + lrh]     = r01;
                VBF[p0 + 2 + lrh] = r10;
                VBF[p1 + 2 + lrh] = r11;
            }
        }
        __syncthreads();   // V fully written; G pads zeroed

#pragma unroll
        for (int nt = 0; nt < 4; nt++)
#pragma unroll
            for (int c = 0; c < 4; c++) acc2[nt][c] = 0.f;
#pragma unroll
        for (int kc = 0; kc < 8; kc++) {
            const int k0 = kc * 16;
            uint32_t a0[4], a1[4];
            a0[0] = __float_as_uint(HWs[(m0 + lr)     * HWS + k0 + lc]);
            a0[1] = __float_as_uint(HWs[(m0 + lr + 8) * HWS + k0 + lc]);
            a0[2] = __float_as_uint(HWs[(m0 + lr)     * HWS + k0 + lc + 4]);
            a0[3] = __float_as_uint(HWs[(m0 + lr + 8) * HWS + k0 + lc + 4]);
            a1[0] = __float_as_uint(HWs[(m0 + lr)     * HWS + k0 + 8 + lc]);
            a1[1] = __float_as_uint(HWs[(m0 + lr + 8) * HWS + k0 + 8 + lc]);
            a1[2] = __float_as_uint(HWs[(m0 + lr)     * HWS + k0 + 12 + lc]);
            a1[3] = __float_as_uint(HWs[(m0 + lr + 8) * HWS + k0 + 12 + lc]);
#pragma unroll
            for (int nt = 0; nt < 4; nt++) {
                float4 bv = *(const float4*)&VBF[((kc << 2) + nt) << 7 | (lid << 2)];
                mma_tf32(acc2[nt], a0, __float_as_uint(bv.x), __float_as_uint(bv.y));
                mma_tf32(acc2[nt], a1, __float_as_uint(bv.z), __float_as_uint(bv.w));
            }
        }

        // ---- fused G = Z2@W1b, P0 = Z2@W0b with z2 in registers ----
        float g0[5], g1[5], p0r[5], p1r[5];
#pragma unroll
        for (int f = 0; f < 5; f++) { g0[f] = 0.f; g1[f] = 0.f; p0r[f] = 0.f; p1r[f] = 0.f; }
#pragma unroll
        for (int nt = 0; nt < 4; nt++) {
            const int h0 = nt * 8 + 2 * lc;
            float z00 = fmaxf(acc[nt][0] + acc2[nt][0], 0.f);
            float z01 = fmaxf(acc[nt][1] + acc2[nt][1], 0.f);
            float z10 = fmaxf(acc[nt][2] + acc2[nt][2], 0.f);
            float z11 = fmaxf(acc[nt][3] + acc2[nt][3], 0.f);
#pragma unroll
            for (int f = 0; f < 5; f++) {
                float wa0 = sw[768 + f * 32 + h0], wa1 = sw[768 + f * 32 + h0 + 1];
                float wb0 = sw[928 + f * 32 + h0], wb1 = sw[928 + f * 32 + h0 + 1];
                g0[f]  += z00 * wb0 + z01 * wb1;
                g1[f]  += z10 * wb0 + z11 * wb1;
                p0r[f] += z00 * wa0 + z01 * wa1;
                p1r[f] += z10 * wa0 + z11 * wa1;
            }
        }
#pragma unroll
        for (int f = 0; f < 5; f++) {
            g0[f]  += __shfl_xor_sync(0xffffffffu, g0[f], 1);
            g0[f]  += __shfl_xor_sync(0xffffffffu, g0[f], 2);
            g1[f]  += __shfl_xor_sync(0xffffffffu, g1[f], 1);
            g1[f]  += __shfl_xor_sync(0xffffffffu, g1[f], 2);
            p0r[f] += __shfl_xor_sync(0xffffffffu, p0r[f], 1);
            p0r[f] += __shfl_xor_sync(0xffffffffu, p0r[f], 2);
            p1r[f] += __shfl_xor_sync(0xffffffffu, p1r[f], 1);
            p1r[f] += __shfl_xor_sync(0xffffffffu, p1r[f], 2);
        }
        if (lc == 0) {
            const int r0 = m0 + lr, r1 = r0 + 8;
#pragma unroll
            for (int f = 0; f < 5; f++) {
                int pos0 = ((r0 >> 4) << 7) | ((f * 4 + (r0 & 3)) << 2) | ((r0 >> 2) & 3);
                int pos1 = ((r1 >> 4) << 7) | ((f * 4 + (r1 & 3)) << 2) | ((r1 >> 2) & 3);
                float gA = g0[f];
                float ghA = __uint_as_float(tf32r(gA));
                Gfh[pos0] = ghA; Gfl[pos0] = gA - ghA;
                float gB = g1[f];
                float ghB = __uint_as_float(tf32r(gB));
                Gfh[pos1] = ghB; Gfl[pos1] = gB - ghB;
                P0[f * 128 + r0] = p0r[f];
                P0[f * 128 + r1] = p1r[f];
            }
        }
    }
    __syncthreads();

    // ====== Phase 5: HWG = HW@G via HMMA (2-term B split) + fused x update ======
    {
        const float* Gfh = U + 4096;
        const float* Gfl = U + 5120;
        const float* P0  = U + 6144;
        float c[4] = {0.f, 0.f, 0.f, 0.f};
#pragma unroll
        for (int kc = 0; kc < 8; kc++) {
            const int k0 = kc * 16;
            uint32_t a0[4], a1[4];
            a0[0] = __float_as_uint(HWs[(m0 + lr)     * HWS + k0 + lc]);
            a0[1] = __float_as_uint(HWs[(m0 + lr + 8) * HWS + k0 + lc]);
            a0[2] = __float_as_uint(HWs[(m0 + lr)     * HWS + k0 + lc + 4]);
            a0[3] = __float_as_uint(HWs[(m0 + lr + 8) * HWS + k0 + lc + 4]);
            a1[0] = __float_as_uint(HWs[(m0 + lr)     * HWS + k0 + 8 + lc]);
            a1[1] = __float_as_uint(HWs[(m0 + lr + 8) * HWS + k0 + 8 + lc]);
            a1[2] = __float_as_uint(HWs[(m0 + lr)     * HWS + k0 + 12 + lc]);
            a1[3] = __float_as_uint(HWs[(m0 + lr + 8) * HWS + k0 + 12 + lc]);
            float4 bh = *(const float4*)&Gfh[(kc << 7) | (lid << 2)];
            float4 bl = *(const float4*)&Gfl[(kc << 7) | (lid << 2)];
            mma_tf32(c, a0, __float_as_uint(bh.x), __float_as_uint(bh.y));
            mma_tf32(c, a1, __float_as_uint(bh.z), __float_as_uint(bh.w));
            mma_tf32(c, a0, __float_as_uint(bl.x), __float_as_uint(bl.y));
            mma_tf32(c, a1, __float_as_uint(bl.z), __float_as_uint(bl.w));
        }
        // fused x update + band-0 partial
        float bs = 0.f;
        const int f0 = 2 * lc, f1 = 2 * lc + 1;
        const int r0 = m0 + lr, r1 = r0 + 8;
        if (f0 < 5) {
            float v0 = xs[f0 * 128 + r0] + P0[f0 * 128 + r0] + c[0];
            float v1 = xs[f0 * 128 + r1] + P0[f0 * 128 + r1] + c[2];
            xs[f0 * 128 + r0] = v0;
            xs[f0 * 128 + r1] = v1;
            if (f0 == 0) bs = v0 + v1;
        }
        if (f1 < 5) {
            float v0 = xs[f1 * 128 + r0] + P0[f1 * 128 + r0] + c[1];
            float v1 = xs[f1 * 128 + r1] + P0[f1 * 128 + r1] + c[3];
            xs[f1 * 128 + r0] = v0;
            xs[f1 * 128 + r1] = v1;
        }
#pragma unroll
        for (int msk = 1; msk <= 16; msk <<= 1)
            bs += __shfl_xor_sync(0xffffffffu, bs, msk);
        if (lid == 0) red[8 + wid] = bs;
    }
    __syncthreads();

    // ===== projection + band clamps + output x (fused) =====
    {
        float fproj = red[8] + red[9] + red[10] + red[11]
                    + red[12] + red[13] + red[14] + red[15] - 10.0f;
        float nu3 = gnu3[0], tg = gtg[0];
        float Vnu = 1.f - 1.f / ((1.f + nu3) * (1.f + nu3));
        float Vg  = 1.f - 1.f / ((1.f + tg) * (1.f + tg));
        float* outx = out + (size_t)b * 640;
        for (int m = tid; m < 640; m += NTHREADS) {
            float v = xs[m];
            int band = m >> 7;
            if (band == 0 && fproj > 0.f) v -= fproj * (1.f / 128.f);
            v = fmaxf(v, band == 1 ? nu3 : 0.f);
            if (band == 2) v = fminf(v, tg);
            if (band == 3) v = fminf(fmaxf(v, Vnu), Vg);
            xs[m] = v;
            outx[m] = v;
        }
    }
    __syncthreads();

    // ================= dacc partials + final outputs =================
    {
        float* dp = U + 6784;
        const int k = tid & 127, q = tid >> 7;
        float a = 0.f;
#pragma unroll 8
        for (int i = 64 * q; i < 64 * q + 64; i++)
            a += xs[i] * HWs[i * HWS + k];
        dp[q * 128 + k] = a;
    }
    __syncthreads();
    {
        const float* dp = U + 6784;
        const size_t BM = (size_t)Bsz * 640;
        const size_t BK = (size_t)Bsz * 128;
        if (tid < 128) {
            int k = tid;
            float p  = xs[k];
            float nu = xs[128 + k];
            float xg = xs[256 + k];
            float xv = xs[384 + k];
            float s4 = xs[512 + k];
            float f5 = 1.f - 1.f / ((1.f + xg) * (1.f + xg)) - xv;
            float f6 = sqrtf(xv) - s4;
            float dacc = dp[k] + dp[128 + k];
            float top  = p * HWs[k * HWS + k];
            float down = dacc - top + 1.f;
            out[BM +            (size_t)b * 128 + k] = f5;
            out[BM +     BK +   (size_t)b * 128 + k] = f6;
            out[BM + 2 * BK +   (size_t)b * 128 + k] = top - down * xg;
            out[BM + 3 * BK +   (size_t)b * 128 + k] = nu * down - top;
        }
    }
}

extern "C" void kernel_launch(void* const* d_in, const int* in_sizes, int n_in,
                              void* d_out, int out_size) {
    const float* HW    = (const float*)d_in[2];
    const float* x0    = (const float*)d_in[3];
    const float* nu3   = (const float*)d_in[4];
    const float* tg    = (const float*)d_in[5];
    const float* g1W0a = (const float*)d_in[12];
    const float* g1W1a = (const float*)d_in[13];
    const float* g1W0b = (const float*)d_in[14];
    const float* g1W1b = (const float*)d_in[15];
    const float* g2W0a = (const float*)d_in[16];
    const float* g2W1a = (const float*)d_in[17];
    const float* g2W0b = (const float*)d_in[18];
    const float* g2W1b = (const float*)d_in[19];

    cudaFuncSetAttribute(unfold_pocs_kernel,
                         cudaFuncAttributeMaxDynamicSharedMemorySize, SMEM_BYTES);

    unfold_pocs_kernel<<<Bsz, NTHREADS, SMEM_BYTES>>>(
        HW, x0, nu3, tg,
        g1W0a, g1W1a, g1W0b, g1W1b,
        g2W0a, g2W1a, g2W0b, g2W1b,
        (float*)d_out);
}

// round 16
// speedup vs baseline: 1.1364x; 1.0250x over previous
#include <cuda_runtime.h>
#include <math.h>
#include <stdint.h>

#define Bsz 2048
#define NTHREADS 256
#define HWS 132

typedef unsigned long long ull;

// ---- smem layout (float offsets) ----
#define O_HW   0        // 16896 : HW row-major stride 132
#define O_U    16896    // 9216 union region:
                        //  phase0/1: WBF (W64 frag) 8192 @ +0 ; X1t frag 1024 @ +8192
                        //  GNN1 : Wct frag 512 @ +5376 ; part 512 @ +5888 ; cpart 1024 @ +6400
                        //  ph2/3/5: VBF frag 4096 @ +0 ; Gfh 1024 @ +4096 ; Gfl 1024 @ +5120 ;
                        //           P0 640 @ +6144 ; dp 1024 @ +6784
#define O_XS   26112    // 640
#define O_SX1  26752    // 640 (SX1 only)
#define O_SW   27392    // 1088
#define O_RED  28608    // 64
#define SMEM_FLOATS 28672
#define SMEM_BYTES (SMEM_FLOATS * 4)   // 114688 B -> 2 CTAs/SM

__device__ __forceinline__ uint32_t tf32r(float x) {
    uint32_t u; asm("cvt.rna.tf32.f32 %0, %1;" : "=r"(u) : "f"(x)); return u;
}
__device__ __forceinline__ void mma_tf32(float* c, const uint32_t* a, uint32_t b0, uint32_t b1) {
    asm volatile(
        "mma.sync.aligned.m16n8k8.row.col.f32.tf32.tf32.f32 "
        "{%0,%1,%2,%3}, {%4,%5,%6,%7}, {%8,%9}, {%0,%1,%2,%3};"
        : "+f"(c[0]), "+f"(c[1]), "+f"(c[2]), "+f"(c[3])
        : "r"(a[0]), "r"(a[1]), "r"(a[2]), "r"(a[3]), "r"(b0), "r"(b1));
}

__global__ __launch_bounds__(NTHREADS, 2)
void unfold_pocs_kernel(const float* __restrict__ gHW, const float* __restrict__ gx0,
                        const float* __restrict__ gnu3, const float* __restrict__ gtg,
                        const float* __restrict__ g1W0a, const float* __restrict__ g1W1a,
                        const float* __restrict__ g1W0b, const float* __restrict__ g1W1b,
                        const float* __restrict__ g2W0a, const float* __restrict__ g2W1a,
                        const float* __restrict__ g2W0b, const float* __restrict__ g2W1b,
                        float* __restrict__ out) {
    extern __shared__ float sm[];
    const int b = blockIdx.x;
    const int tid = threadIdx.x;
    const int wid = tid >> 5;
    const int lid = tid & 31;
    const int lr = lid >> 2;   // 0..7
    const int lc = lid & 3;    // 0..3

    float* HWs = sm + O_HW;
    float* U   = sm + O_U;
    float* xs  = sm + O_XS;
    float* sx1 = sm + O_SX1;
    float* sw  = sm + O_SW;
    float* red = sm + O_RED;

    const float* hwg = gHW + (size_t)b * (128 * 128);

    // ================= Phase 0: loads =================
    for (int o = tid; o < 4096; o += NTHREADS) {
        float4 v = *(const float4*)(hwg + o * 4);
        int w = o * 4;
        int row = w >> 7, col = w & 127;
        *(float4*)&HWs[row * HWS + col] = v;
    }
    for (int o = tid; o < 160; o += NTHREADS)
        *(float4*)&xs[o * 4] = *(const float4*)(gx0 + (size_t)b * 640 + o * 4);
    // W64 fragment build: conflict-free float4 STS (chunk-lane identity)
    {
        float* WBF = U;
        for (int o = tid; o < 2048; o += NTHREADS) {
            int chunk = o >> 5, lane = o & 31;
            int kc = chunk >> 3, nt = chunk & 7;
            int k3 = lane & 3, hq = lane >> 2;
            const float* src = (nt < 4) ? (g2W0a + (nt * 8 + hq)) : (g2W1a + ((nt - 4) * 8 + hq));
            int kbase = kc * 16 + k3;
            float4 v;
            v.x = src[(kbase)      * 32];
            v.y = src[(kbase + 4)  * 32];
            v.z = src[(kbase + 8)  * 32];
            v.w = src[(kbase + 12) * 32];
            *(float4*)&WBF[(chunk << 7) + (lane << 2)] = v;
        }
    }
    // X1t frag build (N=8): conflict-free float4 STS
    {
        float* X1t = U + 8192;
        const float* gx = gx0 + (size_t)b * 640;
        for (int o = tid; o < 256; o += NTHREADS) {
            int chunk = o >> 5, lane = o & 31;     // chunk = kc
            int k3 = lane & 3, f = lane >> 2;
            int kbase = chunk * 16 + k3;
            float4 v = make_float4(0.f, 0.f, 0.f, 0.f);
            if (f < 5) {
                const float* src = gx + f * 128;
                v.x = src[kbase];
                v.y = src[kbase + 4];
                v.z = src[kbase + 8];
                v.w = src[kbase + 12];
            }
            *(float4*)&X1t[(chunk << 7) + (lane << 2)] = v;
        }
    }
    for (int o = tid; o < 160; o += NTHREADS) sw[o]       = g1W0a[o];
    for (int o = tid; o < 160; o += NTHREADS) sw[160 + o] = g1W1a[o];
    for (int o = tid; o < 64;  o += NTHREADS) sw[320 + o] = g1W0b[o];
    for (int o = tid; o < 64;  o += NTHREADS) sw[384 + o] = g1W1b[o];
    for (int o = tid; o < 160; o += NTHREADS) sw[448 + o] = g2W0a[128 * 32 + o];
    for (int o = tid; o < 160; o += NTHREADS) sw[608 + o] = g2W1a[128 * 32 + o];
    for (int o = tid; o < 160; o += NTHREADS) {
        int f = o >> 5, h = o & 31;
        sw[768 + f * 32 + h] = g2W0b[h * 5 + f];
        sw[928 + f * 32 + h] = g2W1b[h * 5 + f];
    }
    __syncthreads();

    float acc[8][4];     // T fragments, then U0 in acc[0..3]
    float acc2[4][4];    // phase1: acc2[0] = SX1 tile ; later HW@V fragments
    const int m0 = wid * 16;

    // ================= Phase 1: [T | SX1] = HW @ [W64 | X1] via HMMA tf32 =================
    {
        const float* WBF = U;
        const float* X1t = U + 8192;
#pragma unroll
        for (int nt = 0; nt < 8; nt++)
#pragma unroll
            for (int c = 0; c < 4; c++) acc[nt][c] = 0.f;
#pragma unroll
        for (int c = 0; c < 4; c++) acc2[0][c] = 0.f;
#pragma unroll
        for (int kc = 0; kc < 8; kc++) {
            const int k0 = kc * 16;
            uint32_t a0[4], a1[4];
            a0[0] = __float_as_uint(HWs[(m0 + lr)     * HWS + k0 + lc]);
            a0[1] = __float_as_uint(HWs[(m0 + lr + 8) * HWS + k0 + lc]);
            a0[2] = __float_as_uint(HWs[(m0 + lr)     * HWS + k0 + lc + 4]);
            a0[3] = __float_as_uint(HWs[(m0 + lr + 8) * HWS + k0 + lc + 4]);
            a1[0] = __float_as_uint(HWs[(m0 + lr)     * HWS + k0 + 8 + lc]);
            a1[1] = __float_as_uint(HWs[(m0 + lr + 8) * HWS + k0 + 8 + lc]);
            a1[2] = __float_as_uint(HWs[(m0 + lr)     * HWS + k0 + 12 + lc]);
            a1[3] = __float_as_uint(HWs[(m0 + lr + 8) * HWS + k0 + 12 + lc]);
#pragma unroll
            for (int nt = 0; nt < 8; nt++) {
                float4 bv = *(const float4*)&WBF[((kc << 3) + nt) << 7 | (lid << 2)];
                mma_tf32(acc[nt], a0, __float_as_uint(bv.x), __float_as_uint(bv.y));
                mma_tf32(acc[nt], a1, __float_as_uint(bv.z), __float_as_uint(bv.w));
            }
            {
                float4 bv = *(const float4*)&X1t[(kc << 7) | (lid << 2)];
                mma_tf32(acc2[0], a0, __float_as_uint(bv.x), __float_as_uint(bv.y));
                mma_tf32(acc2[0], a1, __float_as_uint(bv.z), __float_as_uint(bv.w));
            }
        }
        int f0 = 2 * lc, f1 = 2 * lc + 1;
        if (f0 < 5) {
            sx1[f0 * 128 + m0 + lr]     = acc2[0][0];
            sx1[f0 * 128 + m0 + lr + 8] = acc2[0][2];
        }
        if (f1 < 5) {
            sx1[f1 * 128 + m0 + lr]     = acc2[0][1];
            sx1[f1 * 128 + m0 + lr + 8] = acc2[0][3];
        }
    }
    __syncthreads();   // WBF/X1t dead; sx1 = SX1 ready

    // ================= GNN1 (HMMA, Z1 reduced in registers) =================
    {
        float* Wct   = U + 5376;   // cat-weights frag (k=16, N=32)
        float* part  = U + 5888;   // 512: warp partials (sums | wsums)
        float* cpart = U + 6400;   // 1024: colmean partials [rg][128]

        for (int o = tid; o < 128; o += NTHREADS) {
            int chunk = o >> 5, lane = o & 31;   // chunk = h>>3 (0..3)
            int k3 = lane & 3, hq = lane >> 2;
            int h = chunk * 8 + hq;
            float4 v;
#pragma unroll
            for (int c = 0; c < 4; c++) {
                int k = k3 + 4 * c;
                float x = (k < 5) ? sw[k * 32 + h] : (k < 10 ? sw[160 + (k - 5) * 32 + h] : 0.f);
                ((float*)&v)[c] = x;
            }
            *(float4*)&Wct[(chunk << 7) + (lane << 2)] = v;
        }
        // colmean partials: vectorized, (rg=wid, kq=lid)
        {
            const int rbase = wid * 16;
            float4 s = make_float4(0.f, 0.f, 0.f, 0.f);
#pragma unroll 4
            for (int i = rbase; i < rbase + 16; i++) {
                float4 h = *(const float4*)&HWs[i * HWS + 4 * lid];
                s.x += h.x; s.y += h.y; s.z += h.z; s.w += h.w;
            }
            *(float4*)&cpart[wid * 128 + 4 * lid] = s;
        }
        __syncthreads();

        // Z1 = relu(cat @ Wct) via HMMA; reduce rows in registers
        {
            const int row0 = m0 + lr, row1 = row0 + 8;
            float cm0 = 0.f, cm1 = 0.f;
#pragma unroll
            for (int rg = 0; rg < 8; rg++) {
                cm0 += cpart[rg * 128 + row0];
                cm1 += cpart[rg * 128 + row1];
            }
            float cr0 = cm0 * (1.f / 128.f);
            float cr1 = cm1 * (1.f / 128.f);
            uint32_t a0[4], a1[4];
            a0[0] = __float_as_uint(xs[lc * 128 + row0]);
            a0[1] = __float_as_uint(xs[lc * 128 + row1]);
            a0[2] = __float_as_uint((lc == 0) ? xs[4 * 128 + row0] : sx1[(lc - 1) * 128 + row0]);
            a0[3] = __float_as_uint((lc == 0) ? xs[4 * 128 + row1] : sx1[(lc - 1) * 128 + row1]);
            a1[0] = (lc < 2) ? __float_as_uint(sx1[(lc + 3) * 128 + row0]) : 0u;
            a1[1] = (lc < 2) ? __float_as_uint(sx1[(lc + 3) * 128 + row1]) : 0u;
            a1[2] = 0u;
            a1[3] = 0u;
#pragma unroll
            for (int nt = 0; nt < 4; nt++) {
                float cz[4] = {0.f, 0.f, 0.f, 0.f};
                float4 bv = *(const float4*)&Wct[(nt << 7) | (lid << 2)];
                mma_tf32(cz, a0, __float_as_uint(bv.x), __float_as_uint(bv.y));
                mma_tf32(cz, a1, __float_as_uint(bv.z), __float_as_uint(bv.w));
                float r0 = fmaxf(cz[0], 0.f), r1 = fmaxf(cz[1], 0.f);
                float r2 = fmaxf(cz[2], 0.f), r3 = fmaxf(cz[3], 0.f);
                float s0 = r0 + r2, s1 = r1 + r3;
                float w0 = cr0 * r0 + cr1 * r2, w1 = cr0 * r1 + cr1 * r3;
#pragma unroll
                for (int msk = 4; msk <= 16; msk <<= 1) {
                    s0 += __shfl_xor_sync(0xffffffffu, s0, msk);
                    s1 += __shfl_xor_sync(0xffffffffu, s1, msk);
                    w0 += __shfl_xor_sync(0xffffffffu, w0, msk);
                    w1 += __shfl_xor_sync(0xffffffffu, w1, msk);
                }
                if (lr == 0) {
                    part[wid * 32 + nt * 8 + 2 * lc]           = s0;
                    part[wid * 32 + nt * 8 + 2 * lc + 1]       = s1;
                    part[256 + wid * 32 + nt * 8 + 2 * lc]     = w0;
                    part[256 + wid * 32 + nt * 8 + 2 * lc + 1] = w1;
                }
            }
        }
        __syncthreads();
        // fused combine + lbd (warp 0)
        if (tid < 32) {
            float m = 0.f, cz = 0.f;
#pragma unroll
            for (int q = 0; q < 8; q++) {
                m  += part[q * 32 + tid];
                cz += part[256 + q * 32 + tid];
            }
            m *= (1.f / 128.f);
            float l0 = m * sw[320 + tid * 2]     + cz * sw[384 + tid * 2];
            float l1 = m * sw[320 + tid * 2 + 1] + cz * sw[384 + tid * 2 + 1];
#pragma unroll
            for (int msk = 16; msk > 0; msk >>= 1) {
                l0 += __shfl_xor_sync(0xffffffffu, l0, msk);
                l1 += __shfl_xor_sync(0xffffffffu, l1, msk);
            }
            if (tid == 0) {
                red[62] = fmaxf(l0, 0.f);
                red[63] = fmaxf(l1, 0.f);
            }
        }
        __syncthreads();
        if (tid < 128) {
            float l0 = red[62], l1 = red[63];
            float s1v = xs[128 + tid];
            xs[128 + tid] = s1v - l0 * ((1.0f / 128.f) / (1.f + s1v));
            xs[512 + tid] += l1 * ((1.0f / 128.f) * 0.1f);
        }
    }
    __syncthreads();   // xs final

    // ====== Phase 2+3 (+fused G/P0): U0 in regs, V frag, HMMA HW@V, reg-z2 ======
    {
        float* VBF = U;            // V fragment order (N=32 -> 4 n-tiles)
        float* Gfh = U + 4096;
        float* Gfl = U + 5120;
        float* P0  = U + 6144;
        const float* w0bot = sw + 448;
        const float* w1bot = sw + 608;

        // zero G fragment pads (overwritten below for f<5)
        for (int o = tid; o < 512; o += NTHREADS)
            *(float4*)&U[4096 + o * 4] = make_float4(0.f, 0.f, 0.f, 0.f);

        float xr[2][5];
#pragma unroll
        for (int f = 0; f < 5; f++) {
            xr[0][f] = xs[f * 128 + m0 + lr];
            xr[1][f] = xs[f * 128 + m0 + lr + 8];
        }
        const int lr3 = lr & 3, lrh = lr >> 2;
#pragma unroll
        for (int nt = 0; nt < 8; nt++) {
            const bool isU = nt < 4;
            const float* wb = isU ? w0bot : w1bot;
            const int hb = (isU ? nt : nt - 4) * 8 + 2 * lc;
            float r00 = acc[nt][0], r01 = acc[nt][1];
            float r10 = acc[nt][2], r11 = acc[nt][3];
#pragma unroll
            for (int f = 0; f < 5; f++) {
                float w0 = wb[f * 32 + hb], w1 = wb[f * 32 + hb + 1];
                r00 += xr[0][f] * w0; r01 += xr[0][f] * w1;
                r10 += xr[1][f] * w0; r11 += xr[1][f] * w1;
            }
            if (isU) {
                acc[nt][0] = r00; acc[nt][1] = r01; acc[nt][2] = r10; acc[nt][3] = r11;
            } else {
                const int ch = ((wid * 4) + (nt - 4)) << 7;
                const int p0 = ch | (((2 * lc) * 4 + lr3) << 2);
                const int p1 = ch | (((2 * lc + 1) * 4 + lr3) << 2);
                VBF[p0 + lrh]     = r00;
                VBF[p1 + lrh]     = r01;
                VBF[p0 + 2 + lrh] = r10;
                VBF[p1 + 2 + lrh] = r11;
            }
        }
        __syncthreads();   // V fully written; G pads zeroed

#pragma unroll
        for (int nt = 0; nt < 4; nt++)
#pragma unroll
            for (int c = 0; c < 4; c++) acc2[nt][c] = 0.f;
#pragma unroll
        for (int kc = 0; kc < 8; kc++) {
            const int k0 = kc * 16;
            uint32_t a0[4], a1[4];
            a0[0] = __float_as_uint(HWs[(m0 + lr)     * HWS + k0 + lc]);
            a0[1] = __float_as_uint(HWs[(m0 + lr + 8) * HWS + k0 + lc]);
            a0[2] = __float_as_uint(HWs[(m0 + lr)     * HWS + k0 + lc + 4]);
            a0[3] = __float_as_uint(HWs[(m0 + lr + 8) * HWS + k0 + lc + 4]);
            a1[0] = __float_as_uint(HWs[(m0 + lr)     * HWS + k0 + 8 + lc]);
            a1[1] = __float_as_uint(HWs[(m0 + lr + 8) * HWS + k0 + 8 + lc]);
            a1[2] = __float_as_uint(HWs[(m0 + lr)     * HWS + k0 + 12 + lc]);
            a1[3] = __float_as_uint(HWs[(m0 + lr + 8) * HWS + k0 + 12 + lc]);
#pragma unroll
            for (int nt = 0; nt < 4; nt++) {
                float4 bv = *(const float4*)&VBF[((kc << 2) + nt) << 7 | (lid << 2)];
                mma_tf32(acc2[nt], a0, __float_as_uint(bv.x), __float_as_uint(bv.y));
                mma_tf32(acc2[nt], a1, __float_as_uint(bv.z), __float_as_uint(bv.w));
            }
        }

        // ---- fused G = Z2@W1b, P0 = Z2@W0b with z2 in registers ----
        float g0[5], g1[5], p0r[5], p1r[5];
#pragma unroll
        for (int f = 0; f < 5; f++) { g0[f] = 0.f; g1[f] = 0.f; p0r[f] = 0.f; p1r[f] = 0.f; }
#pragma unroll
        for (int nt = 0; nt < 4; nt++) {
            const int h0 = nt * 8 + 2 * lc;
            float z00 = fmaxf(acc[nt][0] + acc2[nt][0], 0.f);
            float z01 = fmaxf(acc[nt][1] + acc2[nt][1], 0.f);
            float z10 = fmaxf(acc[nt][2] + acc2[nt][2], 0.f);
            float z11 = fmaxf(acc[nt][3] + acc2[nt][3], 0.f);
#pragma unroll
            for (int f = 0; f < 5; f++) {
                float wa0 = sw[768 + f * 32 + h0], wa1 = sw[768 + f * 32 + h0 + 1];
                float wb0 = sw[928 + f * 32 + h0], wb1 = sw[928 + f * 32 + h0 + 1];
                g0[f]  += z00 * wb0 + z01 * wb1;
                g1[f]  += z10 * wb0 + z11 * wb1;
                p0r[f] += z00 * wa0 + z01 * wa1;
                p1r[f] += z10 * wa0 + z11 * wa1;
            }
        }
#pragma unroll
        for (int f = 0; f < 5; f++) {
            g0[f]  += __shfl_xor_sync(0xffffffffu, g0[f], 1);
            g0[f]  += __shfl_xor_sync(0xffffffffu, g0[f], 2);
            g1[f]  += __shfl_xor_sync(0xffffffffu, g1[f], 1);
            g1[f]  += __shfl_xor_sync(0xffffffffu, g1[f], 2);
            p0r[f] += __shfl_xor_sync(0xffffffffu, p0r[f], 1);
            p0r[f] += __shfl_xor_sync(0xffffffffu, p0r[f], 2);
            p1r[f] += __shfl_xor_sync(0xffffffffu, p1r[f], 1);
            p1r[f] += __shfl_xor_sync(0xffffffffu, p1r[f], 2);
        }
        if (lc == 0) {
            const int r0 = m0 + lr, r1 = r0 + 8;
#pragma unroll
            for (int f = 0; f < 5; f++) {
                int pos0 = ((r0 >> 4) << 7) | ((f * 4 + (r0 & 3)) << 2) | ((r0 >> 2) & 3);
                int pos1 = ((r1 >> 4) << 7) | ((f * 4 + (r1 & 3)) << 2) | ((r1 >> 2) & 3);
                float gA = g0[f];
                float ghA = __uint_as_float(tf32r(gA));
                Gfh[pos0] = ghA; Gfl[pos0] = gA - ghA;
                float gB = g1[f];
                float ghB = __uint_as_float(tf32r(gB));
                Gfh[pos1] = ghB; Gfl[pos1] = gB - ghB;
                P0[f * 128 + r0] = p0r[f];
                P0[f * 128 + r1] = p1r[f];
            }
        }
    }
    __syncthreads();

    // ====== Phase 5: HWG = HW@G via HMMA (2-term B split) + fused x update ======
    {
        const float* Gfh = U + 4096;
        const float* Gfl = U + 5120;
        const float* P0  = U + 6144;
        float c[4] = {0.f, 0.f, 0.f, 0.f};
#pragma unroll
        for (int kc = 0; kc < 8; kc++) {
            const int k0 = kc * 16;
            uint32_t a0[4], a1[4];
            a0[0] = __float_as_uint(HWs[(m0 + lr)     * HWS + k0 + lc]);
            a0[1] = __float_as_uint(HWs[(m0 + lr + 8) * HWS + k0 + lc]);
            a0[2] = __float_as_uint(HWs[(m0 + lr)     * HWS + k0 + lc + 4]);
            a0[3] = __float_as_uint(HWs[(m0 + lr + 8) * HWS + k0 + lc + 4]);
            a1[0] = __float_as_uint(HWs[(m0 + lr)     * HWS + k0 + 8 + lc]);
            a1[1] = __float_as_uint(HWs[(m0 + lr + 8) * HWS + k0 + 8 + lc]);
            a1[2] = __float_as_uint(HWs[(m0 + lr)     * HWS + k0 + 12 + lc]);
            a1[3] = __float_as_uint(HWs[(m0 + lr + 8) * HWS + k0 + 12 + lc]);
            float4 bh = *(const float4*)&Gfh[(kc << 7) | (lid << 2)];
            float4 bl = *(const float4*)&Gfl[(kc << 7) | (lid << 2)];
            mma_tf32(c, a0, __float_as_uint(bh.x), __float_as_uint(bh.y));
            mma_tf32(c, a1, __float_as_uint(bh.z), __float_as_uint(bh.w));
            mma_tf32(c, a0, __float_as_uint(bl.x), __float_as_uint(bl.y));
            mma_tf32(c, a1, __float_as_uint(bl.z), __float_as_uint(bl.w));
        }
        // fused x update + band-0 partial
        float bs = 0.f;
        const int f0 = 2 * lc, f1 = 2 * lc + 1;
        const int r0 = m0 + lr, r1 = r0 + 8;
        if (f0 < 5) {
            float v0 = xs[f0 * 128 + r0] + P0[f0 * 128 + r0] + c[0];
            float v1 = xs[f0 * 128 + r1] + P0[f0 * 128 + r1] + c[2];
            xs[f0 * 128 + r0] = v0;
            xs[f0 * 128 + r1] = v1;
            if (f0 == 0) bs = v0 + v1;
        }
        if (f1 < 5) {
            float v0 = xs[f1 * 128 + r0] + P0[f1 * 128 + r0] + c[1];
            float v1 = xs[f1 * 128 + r1] + P0[f1 * 128 + r1] + c[3];
            xs[f1 * 128 + r0] = v0;
            xs[f1 * 128 + r1] = v1;
        }
#pragma unroll
        for (int msk = 1; msk <= 16; msk <<= 1)
            bs += __shfl_xor_sync(0xffffffffu, bs, msk);
        if (lid == 0) red[8 + wid] = bs;
    }
    __syncthreads();

    // ===== projection + band clamps + output x (fused) =====
    {
        float fproj = red[8] + red[9] + red[10] + red[11]
                    + red[12] + red[13] + red[14] + red[15] - 10.0f;
        float nu3 = gnu3[0], tg = gtg[0];
        float Vnu = 1.f - 1.f / ((1.f + nu3) * (1.f + nu3));
        float Vg  = 1.f - 1.f / ((1.f + tg) * (1.f + tg));
        float* outx = out + (size_t)b * 640;
        for (int m = tid; m < 640; m += NTHREADS) {
            float v = xs[m];
            int band = m >> 7;
            if (band == 0 && fproj > 0.f) v -= fproj * (1.f / 128.f);
            v = fmaxf(v, band == 1 ? nu3 : 0.f);
            if (band == 2) v = fminf(v, tg);
            if (band == 3) v = fminf(fmaxf(v, Vnu), Vg);
            xs[m] = v;
            outx[m] = v;
        }
    }
    __syncthreads();

    // ================= dacc partials (vectorized) + final outputs =================
    {
        float* dp = U + 6784;
        const int rbase = wid * 16;
        float4 s = make_float4(0.f, 0.f, 0.f, 0.f);
#pragma unroll 4
        for (int i = rbase; i < rbase + 16; i++) {
            float xv = xs[i];
            float4 h = *(const float4*)&HWs[i * HWS + 4 * lid];
            s.x += xv * h.x; s.y += xv * h.y; s.z += xv * h.z; s.w += xv * h.w;
        }
        *(float4*)&dp[wid * 128 + 4 * lid] = s;
    }
    __syncthreads();
    {
        const float* dp = U + 6784;
        const size_t BM = (size_t)Bsz * 640;
        const size_t BK = (size_t)Bsz * 128;
        const int k = tid & 127;
        if (tid < 128) {
            // group 0: f4, f2 (needs dacc)
            float p  = xs[k];
            float nu = xs[128 + k];
            float xg = xs[256 + k];
            float dacc = 0.f;
#pragma unroll
            for (int rg = 0; rg < 8; rg++) dacc += dp[rg * 128 + k];
            float top  = p * HWs[k * HWS + k];
            float down = dacc - top + 1.f;
            out[BM + 2 * BK + (size_t)b * 128 + k] = top - down * xg;
            out[BM + 3 * BK + (size_t)b * 128 + k] = nu * down - top;
        } else {
            // group 1: f5, f6
            float xg = xs[256 + k];
            float xv = xs[384 + k];
            float s4 = xs[512 + k];
            float f5 = 1.f - 1.f / ((1.f + xg) * (1.f + xg)) - xv;
            float f6 = sqrtf(xv) - s4;
            out[BM +      (size_t)b * 128 + k] = f5;
            out[BM + BK + (size_t)b * 128 + k] = f6;
        }
    }
}

extern "C" void kernel_launch(void* const* d_in, const int* in_sizes, int n_in,
                              void* d_out, int out_size) {
    const float* HW    = (const float*)d_in[2];
    const float* x0    = (const float*)d_in[3];
    const float* nu3   = (const float*)d_in[4];
    const float* tg    = (const float*)d_in[5];
    const float* g1W0a = (const float*)d_in[12];
    const float* g1W1a = (const float*)d_in[13];
    const float* g1W0b = (const float*)d_in[14];
    const float* g1W1b = (const float*)d_in[15];
    const float* g2W0a = (const float*)d_in[16];
    const float* g2W1a = (const float*)d_in[17];
    const float* g2W0b = (const float*)d_in[18];
    const float* g2W1b = (const float*)d_in[19];

    cudaFuncSetAttribute(unfold_pocs_kernel,
                         cudaFuncAttributeMaxDynamicSharedMemorySize, SMEM_BYTES);

    unfold_pocs_kernel<<<Bsz, NTHREADS, SMEM_BYTES>>>(
        HW, x0, nu3, tg,
        g1W0a, g1W1a, g1W0b, g1W1b,
        g2W0a, g2W1a, g2W0b, g2W1b,
        (float*)d_out);
}

// round 17
// speedup vs baseline: 1.1623x; 1.0228x over previous
#include <cuda_runtime.h>
#include <math.h>
#include <stdint.h>

#define Bsz 2048
#define NTHREADS 256
#define HWS 132

typedef unsigned long long ull;

// ---- smem layout (float offsets) ----
#define O_HW   0        // 16896 : HW row-major stride 132
#define O_U    16896    // 9216 union region:
                        //  phase0/1: WBF (W64 frag) 8192 @ +0 ; X1t frag 1024 @ +8192
                        //  GNN1 : Wct frag 512 @ +5376 ; part 512 @ +5888 ; cpart 1024 @ +6400
                        //  ph2/3/5: VBF frag 4096 @ +0 ; Gfh 1024 @ +4096 ; Gfl 1024 @ +5120 ;
                        //           P0 640 @ +6144 ; dp 1024 @ +6784
#define O_XS   26112    // 640
#define O_SX1  26752    // 640 (SX1 only)
#define O_SW   27392    // 1088
#define O_RED  28608    // 64
#define SMEM_FLOATS 28672
#define SMEM_BYTES (SMEM_FLOATS * 4)   // 114688 B -> 2 CTAs/SM

__device__ __forceinline__ uint32_t tf32r(float x) {
    uint32_t u; asm("cvt.rna.tf32.f32 %0, %1;" : "=r"(u) : "f"(x)); return u;
}
__device__ __forceinline__ void mma_tf32(float* c, const uint32_t* a, uint32_t b0, uint32_t b1) {
    asm volatile(
        "mma.sync.aligned.m16n8k8.row.col.f32.tf32.tf32.f32 "
        "{%0,%1,%2,%3}, {%4,%5,%6,%7}, {%8,%9}, {%0,%1,%2,%3};"
        : "+f"(c[0]), "+f"(c[1]), "+f"(c[2]), "+f"(c[3])
        : "r"(a[0]), "r"(a[1]), "r"(a[2]), "r"(a[3]), "r"(b0), "r"(b1));
}

__global__ __launch_bounds__(NTHREADS, 2)
void unfold_pocs_kernel(const float* __restrict__ gHW, const float* __restrict__ gx0,
                        const float* __restrict__ gnu3, const float* __restrict__ gtg,
                        const float* __restrict__ g1W0a, const float* __restrict__ g1W1a,
                        const float* __restrict__ g1W0b, const float* __restrict__ g1W1b,
                        const float* __restrict__ g2W0a, const float* __restrict__ g2W1a,
                        const float* __restrict__ g2W0b, const float* __restrict__ g2W1b,
                        float* __restrict__ out) {
    extern __shared__ float sm[];
    const int b = blockIdx.x;
    const int tid = threadIdx.x;
    const int wid = tid >> 5;
    const int lid = tid & 31;
    const int lr = lid >> 2;   // 0..7
    const int lc = lid & 3;    // 0..3

    float* HWs = sm + O_HW;
    float* U   = sm + O_U;
    float* xs  = sm + O_XS;
    float* sx1 = sm + O_SX1;
    float* sw  = sm + O_SW;
    float* red = sm + O_RED;

    const float* hwg = gHW + (size_t)b * (128 * 128);

    // ================= Phase 0: loads (+ fused colmean partials) =================
    float4 colsum = make_float4(0.f, 0.f, 0.f, 0.f);
    for (int o = tid; o < 4096; o += NTHREADS) {
        float4 v = *(const float4*)(hwg + o * 4);
        int w = o * 4;
        int row = w >> 7, col = w & 127;
        *(float4*)&HWs[row * HWS + col] = v;
        colsum.x += v.x; colsum.y += v.y; colsum.z += v.z; colsum.w += v.w;
    }
    for (int o = tid; o < 160; o += NTHREADS)
        *(float4*)&xs[o * 4] = *(const float4*)(gx0 + (size_t)b * 640 + o * 4);
    // W64 fragment build: conflict-free float4 STS (chunk-lane identity)
    {
        float* WBF = U;
        for (int o = tid; o < 2048; o += NTHREADS) {
            int chunk = o >> 5, lane = o & 31;
            int kc = chunk >> 3, nt = chunk & 7;
            int k3 = lane & 3, hq = lane >> 2;
            const float* src = (nt < 4) ? (g2W0a + (nt * 8 + hq)) : (g2W1a + ((nt - 4) * 8 + hq));
            int kbase = kc * 16 + k3;
            float4 v;
            v.x = src[(kbase)      * 32];
            v.y = src[(kbase + 4)  * 32];
            v.z = src[(kbase + 8)  * 32];
            v.w = src[(kbase + 12) * 32];
            *(float4*)&WBF[(chunk << 7) + (lane << 2)] = v;
        }
    }
    // X1t frag build (N=8): conflict-free float4 STS
    {
        float* X1t = U + 8192;
        const float* gx = gx0 + (size_t)b * 640;
        for (int o = tid; o < 256; o += NTHREADS) {
            int chunk = o >> 5, lane = o & 31;     // chunk = kc
            int k3 = lane & 3, f = lane >> 2;
            int kbase = chunk * 16 + k3;
            float4 v = make_float4(0.f, 0.f, 0.f, 0.f);
            if (f < 5) {
                const float* src = gx + f * 128;
                v.x = src[kbase];
                v.y = src[kbase + 4];
                v.z = src[kbase + 8];
                v.w = src[kbase + 12];
            }
            *(float4*)&X1t[(chunk << 7) + (lane << 2)] = v;
        }
    }
    for (int o = tid; o < 160; o += NTHREADS) sw[o]       = g1W0a[o];
    for (int o = tid; o < 160; o += NTHREADS) sw[160 + o] = g1W1a[o];
    for (int o = tid; o < 64;  o += NTHREADS) sw[320 + o] = g1W0b[o];
    for (int o = tid; o < 64;  o += NTHREADS) sw[384 + o] = g1W1b[o];
    for (int o = tid; o < 160; o += NTHREADS) sw[448 + o] = g2W0a[128 * 32 + o];
    for (int o = tid; o < 160; o += NTHREADS) sw[608 + o] = g2W1a[128 * 32 + o];
    for (int o = tid; o < 160; o += NTHREADS) {
        int f = o >> 5, h = o & 31;
        sw[768 + f * 32 + h] = g2W0b[h * 5 + f];
        sw[928 + f * 32 + h] = g2W1b[h * 5 + f];
    }
    __syncthreads();

    float acc[8][4];     // T fragments, then U0 in acc[0..3]
    float acc2[4][4];    // phase1: acc2[0] = SX1 tile ; later HW@V fragments
    uint32_t Areg[8][8]; // persistent HW A-fragments (all 8 k-chunks)
    const int m0 = wid * 16;

    // ================= Phase 1: [T | SX1] = HW @ [W64 | X1] via HMMA tf32 =================
    {
        const float* WBF = U;
        const float* X1t = U + 8192;
#pragma unroll
        for (int nt = 0; nt < 8; nt++)
#pragma unroll
            for (int c = 0; c < 4; c++) acc[nt][c] = 0.f;
#pragma unroll
        for (int c = 0; c < 4; c++) acc2[0][c] = 0.f;
#pragma unroll
        for (int kc = 0; kc < 8; kc++) {
            const int k0 = kc * 16;
            Areg[kc][0] = __float_as_uint(HWs[(m0 + lr)     * HWS + k0 + lc]);
            Areg[kc][1] = __float_as_uint(HWs[(m0 + lr + 8) * HWS + k0 + lc]);
            Areg[kc][2] = __float_as_uint(HWs[(m0 + lr)     * HWS + k0 + lc + 4]);
            Areg[kc][3] = __float_as_uint(HWs[(m0 + lr + 8) * HWS + k0 + lc + 4]);
            Areg[kc][4] = __float_as_uint(HWs[(m0 + lr)     * HWS + k0 + 8 + lc]);
            Areg[kc][5] = __float_as_uint(HWs[(m0 + lr + 8) * HWS + k0 + 8 + lc]);
            Areg[kc][6] = __float_as_uint(HWs[(m0 + lr)     * HWS + k0 + 12 + lc]);
            Areg[kc][7] = __float_as_uint(HWs[(m0 + lr + 8) * HWS + k0 + 12 + lc]);
#pragma unroll
            for (int nt = 0; nt < 8; nt++) {
                float4 bv = *(const float4*)&WBF[((kc << 3) + nt) << 7 | (lid << 2)];
                mma_tf32(acc[nt], &Areg[kc][0], __float_as_uint(bv.x), __float_as_uint(bv.y));
                mma_tf32(acc[nt], &Areg[kc][4], __float_as_uint(bv.z), __float_as_uint(bv.w));
            }
            {
                float4 bv = *(const float4*)&X1t[(kc << 7) | (lid << 2)];
                mma_tf32(acc2[0], &Areg[kc][0], __float_as_uint(bv.x), __float_as_uint(bv.y));
                mma_tf32(acc2[0], &Areg[kc][4], __float_as_uint(bv.z), __float_as_uint(bv.w));
            }
        }
        int f0 = 2 * lc, f1 = 2 * lc + 1;
        if (f0 < 5) {
            sx1[f0 * 128 + m0 + lr]     = acc2[0][0];
            sx1[f0 * 128 + m0 + lr + 8] = acc2[0][2];
        }
        if (f1 < 5) {
            sx1[f1 * 128 + m0 + lr]     = acc2[0][1];
            sx1[f1 * 128 + m0 + lr + 8] = acc2[0][3];
        }
    }
    __syncthreads();   // WBF/X1t dead; sx1 = SX1 ready

    // ================= GNN1 (HMMA, Z1 reduced in registers) =================
    {
        float* Wct   = U + 5376;   // cat-weights frag (k=16, N=32)
        float* part  = U + 5888;   // 512: warp partials (sums | wsums)
        float* cpart = U + 6400;   // 1024: colmean partials [rg][128]

        for (int o = tid; o < 128; o += NTHREADS) {
            int chunk = o >> 5, lane = o & 31;   // chunk = h>>3 (0..3)
            int k3 = lane & 3, hq = lane >> 2;
            int h = chunk * 8 + hq;
            float4 v;
#pragma unroll
            for (int c = 0; c < 4; c++) {
                int k = k3 + 4 * c;
                float x = (k < 5) ? sw[k * 32 + h] : (k < 10 ? sw[160 + (k - 5) * 32 + h] : 0.f);
                ((float*)&v)[c] = x;
            }
            *(float4*)&Wct[(chunk << 7) + (lane << 2)] = v;
        }
        // colmean partials from phase-0 registers (rows == wid mod 8, col quad = lid)
        *(float4*)&cpart[wid * 128 + (lid << 2)] = colsum;
        __syncthreads();

        // Z1 = relu(cat @ Wct) via HMMA; reduce rows in registers
        {
            const int row0 = m0 + lr, row1 = row0 + 8;
            float cm0 = 0.f, cm1 = 0.f;
#pragma unroll
            for (int rg = 0; rg < 8; rg++) {
                cm0 += cpart[rg * 128 + row0];
                cm1 += cpart[rg * 128 + row1];
            }
            float cr0 = cm0 * (1.f / 128.f);
            float cr1 = cm1 * (1.f / 128.f);
            uint32_t a0[4], a1[4];
            a0[0] = __float_as_uint(xs[lc * 128 + row0]);
            a0[1] = __float_as_uint(xs[lc * 128 + row1]);
            a0[2] = __float_as_uint((lc == 0) ? xs[4 * 128 + row0] : sx1[(lc - 1) * 128 + row0]);
            a0[3] = __float_as_uint((lc == 0) ? xs[4 * 128 + row1] : sx1[(lc - 1) * 128 + row1]);
            a1[0] = (lc < 2) ? __float_as_uint(sx1[(lc + 3) * 128 + row0]) : 0u;
            a1[1] = (lc < 2) ? __float_as_uint(sx1[(lc + 3) * 128 + row1]) : 0u;
            a1[2] = 0u;
            a1[3] = 0u;
#pragma unroll
            for (int nt = 0; nt < 4; nt++) {
                float cz[4] = {0.f, 0.f, 0.f, 0.f};
                float4 bv = *(const float4*)&Wct[(nt << 7) | (lid << 2)];
                mma_tf32(cz, a0, __float_as_uint(bv.x), __float_as_uint(bv.y));
                mma_tf32(cz, a1, __float_as_uint(bv.z), __float_as_uint(bv.w));
                float r0 = fmaxf(cz[0], 0.f), r1 = fmaxf(cz[1], 0.f);
                float r2 = fmaxf(cz[2], 0.f), r3 = fmaxf(cz[3], 0.f);
                float s0 = r0 + r2, s1 = r1 + r3;
                float w0 = cr0 * r0 + cr1 * r2, w1 = cr0 * r1 + cr1 * r3;
#pragma unroll
                for (int msk = 4; msk <= 16; msk <<= 1) {
                    s0 += __shfl_xor_sync(0xffffffffu, s0, msk);
                    s1 += __shfl_xor_sync(0xffffffffu, s1, msk);
                    w0 += __shfl_xor_sync(0xffffffffu, w0, msk);
                    w1 += __shfl_xor_sync(0xffffffffu, w1, msk);
                }
                if (lr == 0) {
                    part[wid * 32 + nt * 8 + 2 * lc]           = s0;
                    part[wid * 32 + nt * 8 + 2 * lc + 1]       = s1;
                    part[256 + wid * 32 + nt * 8 + 2 * lc]     = w0;
                    part[256 + wid * 32 + nt * 8 + 2 * lc + 1] = w1;
                }
            }
        }
        __syncthreads();
        // fused combine + lbd (warp 0)
        if (tid < 32) {
            float m = 0.f, cz = 0.f;
#pragma unroll
            for (int q = 0; q < 8; q++) {
                m  += part[q * 32 + tid];
                cz += part[256 + q * 32 + tid];
            }
            m *= (1.f / 128.f);
            float l0 = m * sw[320 + tid * 2]     + cz * sw[384 + tid * 2];
            float l1 = m * sw[320 + tid * 2 + 1] + cz * sw[384 + tid * 2 + 1];
#pragma unroll
            for (int msk = 16; msk > 0; msk >>= 1) {
                l0 += __shfl_xor_sync(0xffffffffu, l0, msk);
                l1 += __shfl_xor_sync(0xffffffffu, l1, msk);
            }
            if (tid == 0) {
                red[62] = fmaxf(l0, 0.f);
                red[63] = fmaxf(l1, 0.f);
            }
        }
        __syncthreads();
        if (tid < 128) {
            float l0 = red[62], l1 = red[63];
            float s1v = xs[128 + tid];
            xs[128 + tid] = s1v - l0 * ((1.0f / 128.f) / (1.f + s1v));
            xs[512 + tid] += l1 * ((1.0f / 128.f) * 0.1f);
        }
    }
    __syncthreads();   // xs final

    // ====== Phase 2+3 (+fused G/P0): U0 in regs, V frag, HMMA HW@V, reg-z2 ======
    {
        float* VBF = U;            // V fragment order (N=32 -> 4 n-tiles)
        float* Gfh = U + 4096;
        float* Gfl = U + 5120;
        float* P0  = U + 6144;
        const float* w0bot = sw + 448;
        const float* w1bot = sw + 608;

        // zero G fragment pads (overwritten below for f<5)
        for (int o = tid; o < 512; o += NTHREADS)
            *(float4*)&U[4096 + o * 4] = make_float4(0.f, 0.f, 0.f, 0.f);

        float xr[2][5];
#pragma unroll
        for (int f = 0; f < 5; f++) {
            xr[0][f] = xs[f * 128 + m0 + lr];
            xr[1][f] = xs[f * 128 + m0 + lr + 8];
        }
        const int lr3 = lr & 3, lrh = lr >> 2;
#pragma unroll
        for (int nt = 0; nt < 8; nt++) {
            const bool isU = nt < 4;
            const float* wb = isU ? w0bot : w1bot;
            const int hb = (isU ? nt : nt - 4) * 8 + 2 * lc;
            float r00 = acc[nt][0], r01 = acc[nt][1];
            float r10 = acc[nt][2], r11 = acc[nt][3];
#pragma unroll
            for (int f = 0; f < 5; f++) {
                float w0 = wb[f * 32 + hb], w1 = wb[f * 32 + hb + 1];
                r00 += xr[0][f] * w0; r01 += xr[0][f] * w1;
                r10 += xr[1][f] * w0; r11 += xr[1][f] * w1;
            }
            if (isU) {
                acc[nt][0] = r00; acc[nt][1] = r01; acc[nt][2] = r10; acc[nt][3] = r11;
            } else {
                const int ch = ((wid * 4) + (nt - 4)) << 7;
                const int p0 = ch | (((2 * lc) * 4 + lr3) << 2);
                const int p1 = ch | (((2 * lc + 1) * 4 + lr3) << 2);
                VBF[p0 + lrh]     = r00;
                VBF[p1 + lrh]     = r01;
                VBF[p0 + 2 + lrh] = r10;
                VBF[p1 + 2 + lrh] = r11;
            }
        }
        __syncthreads();   // V fully written; G pads zeroed

#pragma unroll
        for (int nt = 0; nt < 4; nt++)
#pragma unroll
            for (int c = 0; c < 4; c++) acc2[nt][c] = 0.f;
#pragma unroll
        for (int kc = 0; kc < 8; kc++) {
#pragma unroll
            for (int nt = 0; nt < 4; nt++) {
                float4 bv = *(const float4*)&VBF[((kc << 2) + nt) << 7 | (lid << 2)];
                mma_tf32(acc2[nt], &Areg[kc][0], __float_as_uint(bv.x), __float_as_uint(bv.y));
                mma_tf32(acc2[nt], &Areg[kc][4], __float_as_uint(bv.z), __float_as_uint(bv.w));
            }
        }

        // ---- fused G = Z2@W1b, P0 = Z2@W0b with z2 in registers ----
        float g0[5], g1[5], p0r[5], p1r[5];
#pragma unroll
        for (int f = 0; f < 5; f++) { g0[f] = 0.f; g1[f] = 0.f; p0r[f] = 0.f; p1r[f] = 0.f; }
#pragma unroll
        for (int nt = 0; nt < 4; nt++) {
            const int h0 = nt * 8 + 2 * lc;
            float z00 = fmaxf(acc[nt][0] + acc2[nt][0], 0.f);
            float z01 = fmaxf(acc[nt][1] + acc2[nt][1], 0.f);
            float z10 = fmaxf(acc[nt][2] + acc2[nt][2], 0.f);
            float z11 = fmaxf(acc[nt][3] + acc2[nt][3], 0.f);
#pragma unroll
            for (int f = 0; f < 5; f++) {
                float wa0 = sw[768 + f * 32 + h0], wa1 = sw[768 + f * 32 + h0 + 1];
                float wb0 = sw[928 + f * 32 + h0], wb1 = sw[928 + f * 32 + h0 + 1];
                g0[f]  += z00 * wb0 + z01 * wb1;
                g1[f]  += z10 * wb0 + z11 * wb1;
                p0r[f] += z00 * wa0 + z01 * wa1;
                p1r[f] += z10 * wa0 + z11 * wa1;
            }
        }
#pragma unroll
        for (int f = 0; f < 5; f++) {
            g0[f]  += __shfl_xor_sync(0xffffffffu, g0[f], 1);
            g0[f]  += __shfl_xor_sync(0xffffffffu, g0[f], 2);
            g1[f]  += __shfl_xor_sync(0xffffffffu, g1[f], 1);
            g1[f]  += __shfl_xor_sync(0xffffffffu, g1[f], 2);
            p0r[f] += __shfl_xor_sync(0xffffffffu, p0r[f], 1);
            p0r[f] += __shfl_xor_sync(0xffffffffu, p0r[f], 2);
            p1r[f] += __shfl_xor_sync(0xffffffffu, p1r[f], 1);
            p1r[f] += __shfl_xor_sync(0xffffffffu, p1r[f], 2);
        }
        if (lc == 0) {
            const int r0 = m0 + lr, r1 = r0 + 8;
#pragma unroll
            for (int f = 0; f < 5; f++) {
                int pos0 = ((r0 >> 4) << 7) | ((f * 4 + (r0 & 3)) << 2) | ((r0 >> 2) & 3);
                int pos1 = ((r1 >> 4) << 7) | ((f * 4 + (r1 & 3)) << 2) | ((r1 >> 2) & 3);
                float gA = g0[f];
                float ghA = __uint_as_float(tf32r(gA));
                Gfh[pos0] = ghA; Gfl[pos0] = gA - ghA;
                float gB = g1[f];
                float ghB = __uint_as_float(tf32r(gB));
                Gfh[pos1] = ghB; Gfl[pos1] = gB - ghB;
                P0[f * 128 + r0] = p0r[f];
                P0[f * 128 + r1] = p1r[f];
            }
        }
    }
    __syncthreads();

    // ====== Phase 5: HWG = HW@G via HMMA (2-term B split) + fused x update ======
    {
        const float* Gfh = U + 4096;
        const float* Gfl = U + 5120;
        const float* P0  = U + 6144;
        float c[4] = {0.f, 0.f, 0.f, 0.f};
#pragma unroll
        for (int kc = 0; kc < 8; kc++) {
            float4 bh = *(const float4*)&Gfh[(kc << 7) | (lid << 2)];
            float4 bl = *(const float4*)&Gfl[(kc << 7) | (lid << 2)];
            mma_tf32(c, &Areg[kc][0], __float_as_uint(bh.x), __float_as_uint(bh.y));
            mma_tf32(c, &Areg[kc][4], __float_as_uint(bh.z), __float_as_uint(bh.w));
            mma_tf32(c, &Areg[kc][0], __float_as_uint(bl.x), __float_as_uint(bl.y));
            mma_tf32(c, &Areg[kc][4], __float_as_uint(bl.z), __float_as_uint(bl.w));
        }
        // fused x update + band-0 partial
        float bs = 0.f;
        const int f0 = 2 * lc, f1 = 2 * lc + 1;
        const int r0 = m0 + lr, r1 = r0 + 8;
        if (f0 < 5) {
            float v0 = xs[f0 * 128 + r0] + P0[f0 * 128 + r0] + c[0];
            float v1 = xs[f0 * 128 + r1] + P0[f0 * 128 + r1] + c[2];
            xs[f0 * 128 + r0] = v0;
            xs[f0 * 128 + r1] = v1;
            if (f0 == 0) bs = v0 + v1;
        }
        if (f1 < 5) {
            float v0 = xs[f1 * 128 + r0] + P0[f1 * 128 + r0] + c[1];
            float v1 = xs[f1 * 128 + r1] + P0[f1 * 128 + r1] + c[3];
            xs[f1 * 128 + r0] = v0;
            xs[f1 * 128 + r1] = v1;
        }
#pragma unroll
        for (int msk = 1; msk <= 16; msk <<= 1)
            bs += __shfl_xor_sync(0xffffffffu, bs, msk);
        if (lid == 0) red[8 + wid] = bs;
    }
    __syncthreads();

    // ===== projection + band clamps + output x (fused) =====
    {
        float fproj = red[8] + red[9] + red[10] + red[11]
                    + red[12] + red[13] + red[14] + red[15] - 10.0f;
        float nu3 = gnu3[0], tg = gtg[0];
        float Vnu = 1.f - 1.f / ((1.f + nu3) * (1.f + nu3));
        float Vg  = 1.f - 1.f / ((1.f + tg) * (1.f + tg));
        float* outx = out + (size_t)b * 640;
        for (int m = tid; m < 640; m += NTHREADS) {
            float v = xs[m];
            int band = m >> 7;
            if (band == 0 && fproj > 0.f) v -= fproj * (1.f / 128.f);
            v = fmaxf(v, band == 1 ? nu3 : 0.f);
            if (band == 2) v = fminf(v, tg);
            if (band == 3) v = fminf(fmaxf(v, Vnu), Vg);
            xs[m] = v;
            outx[m] = v;
        }
    }
    __syncthreads();

    // ================= dacc partials (vectorized) + final outputs =================
    {
        float* dp = U + 6784;
        const int rbase = wid * 16;
        float4 s = make_float4(0.f, 0.f, 0.f, 0.f);
#pragma unroll 4
        for (int i = rbase; i < rbase + 16; i++) {
            float xv = xs[i];
            float4 h = *(const float4*)&HWs[i * HWS + 4 * lid];
            s.x += xv * h.x; s.y += xv * h.y; s.z += xv * h.z; s.w += xv * h.w;
        }
        *(float4*)&dp[wid * 128 + 4 * lid] = s;
    }
    __syncthreads();
    {
        const float* dp = U + 6784;
        const size_t BM = (size_t)Bsz * 640;
        const size_t BK = (size_t)Bsz * 128;
        const int k = tid & 127;
        if (tid < 128) {
            // group 0: f4, f2 (needs dacc)
            float p  = xs[k];
            float nu = xs[128 + k];
            float xg = xs[256 + k];
            float dacc = 0.f;
#pragma unroll
            for (int rg = 0; rg < 8; rg++) dacc += dp[rg * 128 + k];
            float top  = p * HWs[k * HWS + k];
            float down = dacc - top + 1.f;
            out[BM + 2 * BK + (size_t)b * 128 + k] = top - down * xg;
            out[BM + 3 * BK + (size_t)b * 128 + k] = nu * down - top;
        } else {
            // group 1: f5, f6
            float xg = xs[256 + k];
            float xv = xs[384 + k];
            float s4 = xs[512 + k];
            float f5 = 1.f - 1.f / ((1.f + xg) * (1.f + xg)) - xv;
            float f6 = sqrtf(xv) - s4;
            out[BM +      (size_t)b * 128 + k] = f5;
            out[BM + BK + (size_t)b * 128 + k] = f6;
        }
    }
}

extern "C" void kernel_launch(void* const* d_in, const int* in_sizes, int n_in,
                              void* d_out, int out_size) {
    const float* HW    = (const float*)d_in[2];
    const float* x0    = (const float*)d_in[3];
    const float* nu3   = (const float*)d_in[4];
    const float* tg    = (const float*)d_in[5];
    const float* g1W0a = (const float*)d_in[12];
    const float* g1W1a = (const float*)d_in[13];
    const float* g1W0b = (const float*)d_in[14];
    const float* g1W1b = (const float*)d_in[15];
    const float* g2W0a = (const float*)d_in[16];
    const float* g2W1a = (const float*)d_in[17];
    const float* g2W0b = (const float*)d_in[18];
    const float* g2W1b = (const float*)d_in[19];

    cudaFuncSetAttribute(unfold_pocs_kernel,
                         cudaFuncAttributeMaxDynamicSharedMemorySize, SMEM_BYTES);

    unfold_pocs_kernel<<<Bsz, NTHREADS, SMEM_BYTES>>>(
        HW, x0, nu3, tg,
        g1W0a, g1W1a, g1W0b, g1W1b,
        g2W0a, g2W1a, g2W0b, g2W1b,
        (float*)d_out);
}